// round 5
// baseline (speedup 1.0000x reference)
#include <cuda_runtime.h>
#include <cuda_bf16.h>
#include <cstdint>

// ---------------- problem constants ----------------
#define NB    4
#define DIM   128
#define HEADS 8
#define PPTS  12544
#define CWID  112
#define WIN   7
#define NWX   16
#define WN    256
#define PT    49

// q,k,v: [n][h][win][tok=49][d=128], values pre-rounded to tf32
__device__ float g_q[(size_t)NB * HEADS * WN * PT * DIM];
__device__ float g_k[(size_t)NB * HEADS * WN * PT * DIM];
__device__ float g_v[(size_t)NB * HEADS * WN * PT * DIM];

__device__ __forceinline__ float tf32f(float x) {
    uint32_t u;
    asm("cvt.rna.tf32.f32 %0, %1;" : "=r"(u) : "f"(x));
    return __uint_as_float(u);
}

__device__ __forceinline__ void mma_tf32(float c[4], const uint32_t a[4], const uint32_t b[2]) {
    asm volatile(
        "mma.sync.aligned.m16n8k8.row.col.f32.tf32.tf32.f32 "
        "{%0,%1,%2,%3}, {%4,%5,%6,%7}, {%8,%9}, {%0,%1,%2,%3};\n"
        : "+f"(c[0]), "+f"(c[1]), "+f"(c[2]), "+f"(c[3])
        : "r"(a[0]), "r"(a[1]), "r"(a[2]), "r"(a[3]), "r"(b[0]), "r"(b[1]));
}

__device__ __forceinline__ void cp16(uint32_t smem_addr, const void* gptr) {
    asm volatile("cp.async.cg.shared.global [%0], [%1], 16;" :: "r"(smem_addr), "l"(gptr));
}
__device__ __forceinline__ void cp_commit() {
    asm volatile("cp.async.commit_group;");
}

// ---------------- Kernel A: QKV projection (tf32 mma) + window partition ----------------
__global__ __launch_bounds__(256, 2)
void qkv_kernel(const float* __restrict__ x,
                const float* __restrict__ Wq, const float* __restrict__ bq,
                const float* __restrict__ Wk, const float* __restrict__ bk,
                const float* __restrict__ Wv, const float* __restrict__ bv) {
    __shared__ float As[128][36];   // [o][k]
    __shared__ float Bs[32][136];   // [k][p]

    int z = blockIdx.z;
    int n = z & 3;
    int which = z >> 2;
    const float* W = (which == 0) ? Wq : (which == 1) ? Wk : Wv;
    const float* bvec = (which == 0) ? bq : (which == 1) ? bk : bv;
    float* garr = (which == 0) ? g_q : (which == 1) ? g_k : g_v;
    int h = blockIdx.y;
    int p_base = blockIdx.x * 128;
    const float* xn = x + (size_t)n * DIM * PPTS;

    int tid = threadIdx.x, lane = tid & 31, wid = tid >> 5;
    int g = lane >> 2, t = lane & 3;
    int m0w = (wid >> 2) * 64, n0w = (wid & 3) * 32;

    float acc[4][4][4] = {};

    for (int k0 = 0; k0 < 128; k0 += 32) {
        #pragma unroll
        for (int r = 0; r < 4; r++) {
            int idx = tid + r * 256;
            int oo = idx >> 3, qq = idx & 7;
            float4 w4 = *(const float4*)&W[(size_t)(h * 128 + oo) * 128 + k0 + qq * 4];
            float4 c4 = make_float4(tf32f(w4.x), tf32f(w4.y), tf32f(w4.z), tf32f(w4.w));
            *(float4*)&As[oo][qq * 4] = c4;
        }
        #pragma unroll
        for (int r = 0; r < 4; r++) {
            int idx = tid + r * 256;
            int kk = idx >> 5, pq = idx & 31;
            float4 x4 = *(const float4*)&xn[(size_t)(k0 + kk) * PPTS + p_base + pq * 4];
            float4 c4 = make_float4(tf32f(x4.x), tf32f(x4.y), tf32f(x4.z), tf32f(x4.w));
            *(float4*)&Bs[kk][pq * 4] = c4;
        }
        __syncthreads();
        #pragma unroll
        for (int ks = 0; ks < 4; ks++) {
            uint32_t af[4][4], bf[4][2];
            #pragma unroll
            for (int mf = 0; mf < 4; mf++) {
                int m = m0w + mf * 16;
                af[mf][0] = __float_as_uint(As[m + g][ks * 8 + t]);
                af[mf][1] = __float_as_uint(As[m + g + 8][ks * 8 + t]);
                af[mf][2] = __float_as_uint(As[m + g][ks * 8 + t + 4]);
                af[mf][3] = __float_as_uint(As[m + g + 8][ks * 8 + t + 4]);
            }
            #pragma unroll
            for (int nf = 0; nf < 4; nf++) {
                int nn = n0w + nf * 8 + g;
                bf[nf][0] = __float_as_uint(Bs[ks * 8 + t][nn]);
                bf[nf][1] = __float_as_uint(Bs[ks * 8 + t + 4][nn]);
            }
            #pragma unroll
            for (int mf = 0; mf < 4; mf++)
                #pragma unroll
                for (int nf = 0; nf < 4; nf++)
                    mma_tf32(acc[mf][nf], af[mf], bf[nf]);
        }
        __syncthreads();
    }

    float biasr[4][2];
    #pragma unroll
    for (int mf = 0; mf < 4; mf++)
        #pragma unroll
        for (int rs = 0; rs < 2; rs++)
            biasr[mf][rs] = bvec[h * 128 + m0w + mf * 16 + rs * 8 + g];

    size_t headbase = ((size_t)n * HEADS + h) * WN;

    #pragma unroll
    for (int nf = 0; nf < 4; nf++) {
        #pragma unroll
        for (int cs = 0; cs < 2; cs++) {
            int p = p_base + n0w + nf * 8 + 2 * t + cs;
            int pr = p / CWID, pc = p - pr * CWID;
            int win = (pr / WIN) * NWX + (pc / WIN);
            int tok = (pr % WIN) * WIN + (pc % WIN);
            float* base = garr + ((headbase + win) * PT + tok) * DIM;
            #pragma unroll
            for (int mf = 0; mf < 4; mf++)
                #pragma unroll
                for (int rs = 0; rs < 2; rs++) {
                    int d = m0w + mf * 16 + rs * 8 + g;
                    base[d] = tf32f(acc[mf][nf][rs * 2 + cs] + biasr[mf][rs]);
                }
        }
    }
}

// ---------------- Kernel B: fused attention + output projection ----------------
// Block per (n, win); loops over 8 heads, accumulating out = sum_h Wo_h @ att_h.
// smem float offsets:
#define SQ_OFF  0          // sq  [64][132]  (rows 49..63 garbage, row-contained)
#define SK_OFF  8448       // sk  [56][132]
#define SV_OFF  15840      // sv  [56][132]  (rows 49..55 zeroed once)
#define ATT_OFF 23232      // att [64][132]
#define SS_OFF  31680      // S   [64][56]
#define WO_OFF  35264      // Wo_s[128][132]
#define SB_OFF  52160      // sb  [169]
#define SM_FLOATS 52336    // ~209.3 KB

__global__ __launch_bounds__(256, 1)
void attn_out_kernel(const float* __restrict__ pos_code,
                     const float* __restrict__ Wo, const float* __restrict__ bo,
                     float* __restrict__ out) {
    extern __shared__ float sm[];
    float* sq  = sm + SQ_OFF;
    float* sk  = sm + SK_OFF;
    float* sv  = sm + SV_OFF;
    float* att = sm + ATT_OFF;
    float* S   = sm + SS_OFF;
    float* wo  = sm + WO_OFF;
    float* sb  = sm + SB_OFF;

    int bid = blockIdx.x;
    int w = bid & 255;
    int n = bid >> 8;
    int tid = threadIdx.x, lane = tid & 31, wid = tid >> 5;
    int g = lane >> 2, t = lane & 3;
    int m0 = (wid >> 1) * 16;       // attention j-tile
    int half = wid & 1;             // n-half selector for QK / PV

    uint32_t sq_a  = (uint32_t)__cvta_generic_to_shared(sq);
    uint32_t sk_a  = (uint32_t)__cvta_generic_to_shared(sk);
    uint32_t sv_a  = (uint32_t)__cvta_generic_to_shared(sv);
    uint32_t wo_a  = (uint32_t)__cvta_generic_to_shared(wo);

    size_t winbase = ((size_t)n * HEADS) * WN + w;   // + h*WN per head

    // ---- pre-loop: zero sv pad rows, load bias table, prefetch head 0 qkv ----
    for (int i = tid; i < 7 * 132; i += 256) sv[49 * 132 + i] = 0.f;
    for (int i = tid; i < 169; i += 256) sb[i] = pos_code[i * HEADS + (0)];  // placeholder; reloaded per head below

    {
        const float4* gq4 = (const float4*)(g_q + (winbase) * (PT * DIM));
        const float4* gk4 = (const float4*)(g_k + (winbase) * (PT * DIM));
        const float4* gv4 = (const float4*)(g_v + (winbase) * (PT * DIM));
        for (int i = tid; i < PT * 32; i += 256) {
            int r = i >> 5, c = i & 31;
            uint32_t off = (uint32_t)(r * 132 + c * 4) * 4;
            cp16(sq_a + off, gq4 + i);
            cp16(sk_a + off, gk4 + i);
            cp16(sv_a + off, gv4 + i);
        }
        cp_commit();
    }

    float acc_o[7][4] = {};
    const float scale = 0.08838834764831845f;
    int om0 = wid * 16;

    for (int h = 0; h < 8; h++) {
        asm volatile("cp.async.wait_group 0;");
        __syncthreads();

        // reload per-head bias table (sb region not otherwise touched mid-head)
        for (int i = tid; i < 169; i += 256) sb[i] = pos_code[i * HEADS + h];

        // kick Wo_h copy (overlaps QK/softmax/PV)
        for (int i = tid; i < 4096; i += 256) {
            int r = i >> 5, c = i & 31;
            cp16(wo_a + (uint32_t)(r * 132 + c * 4) * 4, Wo + (size_t)r * 1024 + h * 128 + c * 4);
        }
        cp_commit();

        // ---- QK: S[j][i], m=64(j), n=56(i), k=128 ----
        {
            float acc[4][4] = {};
            #pragma unroll
            for (int ks = 0; ks < 16; ks++) {
                int k0 = ks * 8;
                uint32_t a[4];
                a[0] = __float_as_uint(sq[(m0 + g) * 132 + k0 + t]);
                a[1] = __float_as_uint(sq[(m0 + g + 8) * 132 + k0 + t]);
                a[2] = __float_as_uint(sq[(m0 + g) * 132 + k0 + t + 4]);
                a[3] = __float_as_uint(sq[(m0 + g + 8) * 132 + k0 + t + 4]);
                #pragma unroll
                for (int nt = 0; nt < 4; nt++) {
                    int nti = half * 4 + nt;
                    if (nti >= 7) break;
                    int n0 = nti * 8;
                    uint32_t b[2];
                    b[0] = __float_as_uint(sk[(n0 + g) * 132 + k0 + t]);
                    b[1] = __float_as_uint(sk[(n0 + g) * 132 + k0 + t + 4]);
                    mma_tf32(acc[nt], a, b);
                }
            }
            #pragma unroll
            for (int nt = 0; nt < 4; nt++) {
                int nti = half * 4 + nt;
                if (nti >= 7) break;
                int n0 = nti * 8;
                S[(m0 + g) * 56 + n0 + 2 * t]     = acc[nt][0];
                S[(m0 + g) * 56 + n0 + 2 * t + 1] = acc[nt][1];
                S[(m0 + g + 8) * 56 + n0 + 2 * t]     = acc[nt][2];
                S[(m0 + g + 8) * 56 + n0 + 2 * t + 1] = acc[nt][3];
            }
        }
        __syncthreads();

        // ---- softmax over i per row j (scale + rel-pos bias), pad cols -> 0 ----
        for (int j = wid; j < PT; j += 8) {
            int yj = j / WIN, xj = j - yj * WIN;
            float* row = S + j * 56;
            int i0 = lane;
            int y0 = i0 / WIN, x0 = i0 - y0 * WIN;
            int r0 = (y0 - yj + WIN - 1) + (x0 - xj + WIN - 1) * (2 * WIN - 1);
            float v0 = row[i0] * scale + sb[r0];
            float v1 = -1e30f;
            int i1 = lane + 32;
            if (i1 < PT) {
                int y1 = i1 / WIN, x1 = i1 - y1 * WIN;
                int r1 = (y1 - yj + WIN - 1) + (x1 - xj + WIN - 1) * (2 * WIN - 1);
                v1 = row[i1] * scale + sb[r1];
            }
            float m = fmaxf(v0, v1);
            #pragma unroll
            for (int off = 16; off; off >>= 1) m = fmaxf(m, __shfl_xor_sync(0xffffffffu, m, off));
            float e0 = __expf(v0 - m);
            float e1 = (i1 < PT) ? __expf(v1 - m) : 0.f;
            float s = e0 + e1;
            #pragma unroll
            for (int off = 16; off; off >>= 1) s += __shfl_xor_sync(0xffffffffu, s, off);
            float inv = 1.f / s;
            row[i0] = tf32f(e0 * inv);
            if (i1 < PT) row[i1] = tf32f(e1 * inv);
            else if (i1 < 56) row[i1] = 0.f;
        }
        __syncthreads();

        // ---- PV: att[j][d] = sum_i P[j][i] v[i][d]; m=64(j), n=128(d), k=56 ----
        {
            float acc[8][4] = {};
            #pragma unroll
            for (int ks = 0; ks < 7; ks++) {
                int k0 = ks * 8;
                uint32_t a[4];
                a[0] = __float_as_uint(S[(m0 + g) * 56 + k0 + t]);
                a[1] = __float_as_uint(S[(m0 + g + 8) * 56 + k0 + t]);
                a[2] = __float_as_uint(S[(m0 + g) * 56 + k0 + t + 4]);
                a[3] = __float_as_uint(S[(m0 + g + 8) * 56 + k0 + t + 4]);
                #pragma unroll
                for (int nt = 0; nt < 8; nt++) {
                    int n0 = (half * 8 + nt) * 8;
                    uint32_t b[2];
                    b[0] = __float_as_uint(sv[(k0 + t) * 132 + n0 + g]);
                    b[1] = __float_as_uint(sv[(k0 + t + 4) * 132 + n0 + g]);
                    mma_tf32(acc[nt], a, b);
                }
            }
            #pragma unroll
            for (int nt = 0; nt < 8; nt++) {
                int d0 = (half * 8 + nt) * 8 + 2 * t;
                att[(m0 + g) * 132 + d0]         = tf32f(acc[nt][0]);
                att[(m0 + g) * 132 + d0 + 1]     = tf32f(acc[nt][1]);
                att[(m0 + g + 8) * 132 + d0]     = tf32f(acc[nt][2]);
                att[(m0 + g + 8) * 132 + d0 + 1] = tf32f(acc[nt][3]);
            }
        }
        __syncthreads();

        // prefetch next head's q,k,v into sq/sk/sv (out-stage doesn't touch them)
        if (h < 7) {
            size_t nb = winbase + (size_t)(h + 1) * WN;
            const float4* gq4 = (const float4*)(g_q + nb * (PT * DIM));
            const float4* gk4 = (const float4*)(g_k + nb * (PT * DIM));
            const float4* gv4 = (const float4*)(g_v + nb * (PT * DIM));
            for (int i = tid; i < PT * 32; i += 256) {
                int r = i >> 5, c = i & 31;
                uint32_t off = (uint32_t)(r * 132 + c * 4) * 4;
                cp16(sq_a + off, gq4 + i);
                cp16(sk_a + off, gk4 + i);
                cp16(sv_a + off, gv4 + i);
            }
            cp_commit();
            asm volatile("cp.async.wait_group 1;");   // Wo_h done, qkv_{h+1} in flight
        } else {
            asm volatile("cp.async.wait_group 0;");   // Wo_h done
        }

        // round own Wo chunk to tf32 (rna) in place
        for (int i = tid; i < 4096; i += 256) {
            int r = i >> 5, c = i & 31;
            float4* pwo = (float4*)&wo[r * 132 + c * 4];
            float4 v = *pwo;
            *pwo = make_float4(tf32f(v.x), tf32f(v.y), tf32f(v.z), tf32f(v.w));
        }
        __syncthreads();

        // ---- out accumulate: C[o][tok] += Wo_h[o][d] @ att[tok][d] ----
        #pragma unroll
        for (int ks = 0; ks < 16; ks++) {
            int k0 = ks * 8;
            uint32_t a[4];
            a[0] = __float_as_uint(wo[(om0 + g) * 132 + k0 + t]);
            a[1] = __float_as_uint(wo[(om0 + g + 8) * 132 + k0 + t]);
            a[2] = __float_as_uint(wo[(om0 + g) * 132 + k0 + t + 4]);
            a[3] = __float_as_uint(wo[(om0 + g + 8) * 132 + k0 + t + 4]);
            #pragma unroll
            for (int nt = 0; nt < 7; nt++) {
                uint32_t b[2];
                b[0] = __float_as_uint(att[(nt * 8 + g) * 132 + k0 + t]);
                b[1] = __float_as_uint(att[(nt * 8 + g) * 132 + k0 + t + 4]);
                mma_tf32(acc_o[nt], a, b);
            }
        }
        __syncthreads();   // protect att/wo before next head rewrites
    }

    // ---- final store: out[n][o][p] = acc + bo[o] ----
    int wy = w >> 4, wx = w & 15;
    float* dst_n = out + (size_t)n * DIM * PPTS;
    #pragma unroll
    for (int rs = 0; rs < 2; rs++) {
        int o = om0 + g + rs * 8;
        float bias = bo[o];
        float* dst = dst_n + (size_t)o * PPTS;
        #pragma unroll
        for (int nt = 0; nt < 7; nt++) {
            #pragma unroll
            for (int cs = 0; cs < 2; cs++) {
                int tok = nt * 8 + 2 * t + cs;
                if (tok < PT) {
                    int jy = tok / WIN, jx = tok - jy * WIN;
                    int p = (wy * WIN + jy) * CWID + wx * WIN + jx;
                    dst[p] = acc_o[nt][rs * 2 + cs] + bias;
                }
            }
        }
    }
}

// ---------------- launch ----------------
extern "C" void kernel_launch(void* const* d_in, const int* in_sizes, int n_in,
                              void* d_out, int out_size) {
    const float* x   = (const float*)d_in[0];
    const float* Wq  = (const float*)d_in[1];
    const float* bq  = (const float*)d_in[2];
    const float* Wk  = (const float*)d_in[3];
    const float* bk  = (const float*)d_in[4];
    const float* Wv  = (const float*)d_in[5];
    const float* bv  = (const float*)d_in[6];
    const float* Wo  = (const float*)d_in[7];
    const float* bo  = (const float*)d_in[8];
    const float* pos = (const float*)d_in[9];
    float* out = (float*)d_out;

    {
        dim3 grid(PPTS / 128, HEADS, 12);
        qkv_kernel<<<grid, 256>>>(x, Wq, bq, Wk, bk, Wv, bv);
    }
    {
        const int smem = SM_FLOATS * (int)sizeof(float);   // ~209.3 KB
        static int attr_set = 0;
        if (!attr_set) {
            cudaFuncSetAttribute(attn_out_kernel, cudaFuncAttributeMaxDynamicSharedMemorySize, smem);
            attr_set = 1;
        }
        attn_out_kernel<<<NB * WN, 256, smem>>>(pos, Wo, bo, out);
    }
}

// round 6
// speedup vs baseline: 1.0554x; 1.0554x over previous
#include <cuda_runtime.h>
#include <cuda_bf16.h>
#include <cstdint>

// ---------------- problem constants ----------------
#define NB    4
#define DIM   128
#define HEADS 8
#define PPTS  12544
#define CWID  112
#define WIN   7
#define NWX   16
#define WN    256
#define PT    49

// q,k,v: [n][h][win][tok=49][d=128], values pre-rounded to tf32
__device__ float g_q[(size_t)NB * HEADS * WN * PT * DIM];
__device__ float g_k[(size_t)NB * HEADS * WN * PT * DIM];
__device__ float g_v[(size_t)NB * HEADS * WN * PT * DIM];
__device__ float g_woR[(size_t)DIM * HEADS * DIM];     // Wo rounded to tf32, same layout

__device__ __forceinline__ float tf32f(float x) {
    uint32_t u;
    asm("cvt.rna.tf32.f32 %0, %1;" : "=r"(u) : "f"(x));
    return __uint_as_float(u);
}

__device__ __forceinline__ void mma_tf32(float c[4], const uint32_t a[4], const uint32_t b[2]) {
    asm volatile(
        "mma.sync.aligned.m16n8k8.row.col.f32.tf32.tf32.f32 "
        "{%0,%1,%2,%3}, {%4,%5,%6,%7}, {%8,%9}, {%0,%1,%2,%3};\n"
        : "+f"(c[0]), "+f"(c[1]), "+f"(c[2]), "+f"(c[3])
        : "r"(a[0]), "r"(a[1]), "r"(a[2]), "r"(a[3]), "r"(b[0]), "r"(b[1]));
}

__device__ __forceinline__ void cp16(uint32_t smem_addr, const void* gptr) {
    asm volatile("cp.async.cg.shared.global [%0], [%1], 16;" :: "r"(smem_addr), "l"(gptr));
}
__device__ __forceinline__ void cp_commit() {
    asm volatile("cp.async.commit_group;");
}

// ---------------- Kernel P: round Wo to tf32 into g_woR ----------------
__global__ void wo_prep(const float* __restrict__ Wo) {
    int i = blockIdx.x * 256 + threadIdx.x;     // float4 index, 32768 total
    float4 v = ((const float4*)Wo)[i];
    ((float4*)g_woR)[i] = make_float4(tf32f(v.x), tf32f(v.y), tf32f(v.z), tf32f(v.w));
}

// ---------------- Kernel A: QKV projection (tf32 mma) + window partition ----------------
__global__ __launch_bounds__(256, 2)
void qkv_kernel(const float* __restrict__ x,
                const float* __restrict__ Wq, const float* __restrict__ bq,
                const float* __restrict__ Wk, const float* __restrict__ bk,
                const float* __restrict__ Wv, const float* __restrict__ bv) {
    __shared__ float As[128][36];   // [o][k]
    __shared__ float Bs[32][136];   // [k][p]

    int z = blockIdx.z;
    int n = z & 3;
    int which = z >> 2;
    const float* W = (which == 0) ? Wq : (which == 1) ? Wk : Wv;
    const float* bvec = (which == 0) ? bq : (which == 1) ? bk : bv;
    float* garr = (which == 0) ? g_q : (which == 1) ? g_k : g_v;
    int h = blockIdx.y;
    int p_base = blockIdx.x * 128;
    const float* xn = x + (size_t)n * DIM * PPTS;

    int tid = threadIdx.x, lane = tid & 31, wid = tid >> 5;
    int g = lane >> 2, t = lane & 3;
    int m0w = (wid >> 2) * 64, n0w = (wid & 3) * 32;

    float acc[4][4][4] = {};

    for (int k0 = 0; k0 < 128; k0 += 32) {
        #pragma unroll
        for (int r = 0; r < 4; r++) {
            int idx = tid + r * 256;
            int oo = idx >> 3, qq = idx & 7;
            float4 w4 = *(const float4*)&W[(size_t)(h * 128 + oo) * 128 + k0 + qq * 4];
            float4 c4 = make_float4(tf32f(w4.x), tf32f(w4.y), tf32f(w4.z), tf32f(w4.w));
            *(float4*)&As[oo][qq * 4] = c4;
        }
        #pragma unroll
        for (int r = 0; r < 4; r++) {
            int idx = tid + r * 256;
            int kk = idx >> 5, pq = idx & 31;
            float4 x4 = *(const float4*)&xn[(size_t)(k0 + kk) * PPTS + p_base + pq * 4];
            float4 c4 = make_float4(tf32f(x4.x), tf32f(x4.y), tf32f(x4.z), tf32f(x4.w));
            *(float4*)&Bs[kk][pq * 4] = c4;
        }
        __syncthreads();
        #pragma unroll
        for (int ks = 0; ks < 4; ks++) {
            uint32_t af[4][4], bf[4][2];
            #pragma unroll
            for (int mf = 0; mf < 4; mf++) {
                int m = m0w + mf * 16;
                af[mf][0] = __float_as_uint(As[m + g][ks * 8 + t]);
                af[mf][1] = __float_as_uint(As[m + g + 8][ks * 8 + t]);
                af[mf][2] = __float_as_uint(As[m + g][ks * 8 + t + 4]);
                af[mf][3] = __float_as_uint(As[m + g + 8][ks * 8 + t + 4]);
            }
            #pragma unroll
            for (int nf = 0; nf < 4; nf++) {
                int nn = n0w + nf * 8 + g;
                bf[nf][0] = __float_as_uint(Bs[ks * 8 + t][nn]);
                bf[nf][1] = __float_as_uint(Bs[ks * 8 + t + 4][nn]);
            }
            #pragma unroll
            for (int mf = 0; mf < 4; mf++)
                #pragma unroll
                for (int nf = 0; nf < 4; nf++)
                    mma_tf32(acc[mf][nf], af[mf], bf[nf]);
        }
        __syncthreads();
    }

    float biasr[4][2];
    #pragma unroll
    for (int mf = 0; mf < 4; mf++)
        #pragma unroll
        for (int rs = 0; rs < 2; rs++)
            biasr[mf][rs] = bvec[h * 128 + m0w + mf * 16 + rs * 8 + g];

    size_t headbase = ((size_t)n * HEADS + h) * WN;

    #pragma unroll
    for (int nf = 0; nf < 4; nf++) {
        #pragma unroll
        for (int cs = 0; cs < 2; cs++) {
            int p = p_base + n0w + nf * 8 + 2 * t + cs;
            int pr = p / CWID, pc = p - pr * CWID;
            int win = (pr / WIN) * NWX + (pc / WIN);
            int tok = (pr % WIN) * WIN + (pc % WIN);
            float* base = garr + ((headbase + win) * PT + tok) * DIM;
            #pragma unroll
            for (int mf = 0; mf < 4; mf++)
                #pragma unroll
                for (int rs = 0; rs < 2; rs++) {
                    int d = m0w + mf * 16 + rs * 8 + g;
                    base[d] = tf32f(acc[mf][nf][rs * 2 + cs] + biasr[mf][rs]);
                }
        }
    }
}

// ---------------- Kernel B: fused attention + output projection ----------------
// Block per (n, win); loops heads, out = sum_h Wo_h @ att_h.  2 CTAs/SM.
// smem float offsets:
#define SQ_OFF  0          // sq/att [64][132]  (aliased)
#define SK_OFF  8448       // sk  [56][132]
#define SV_OFF  15840      // sv  [56][132] (rows 49..55 zeroed once)
#define SS_OFF  23232      // S   [64][60]
#define SB_OFF  27072      // sb  [176]
#define SM_FLOATS 27248    // 108,992 B

__global__ __launch_bounds__(256, 2)
void attn_out_kernel(const float* __restrict__ pos_code,
                     const float* __restrict__ bo,
                     float* __restrict__ out) {
    extern __shared__ float sm[];
    float* sq  = sm + SQ_OFF;
    float* sk  = sm + SK_OFF;
    float* sv  = sm + SV_OFF;
    float* att = sm + SQ_OFF;       // alias: q dead after QK
    float* S   = sm + SS_OFF;
    float* sb  = sm + SB_OFF;

    int bid = blockIdx.x;
    int w = bid & 255;
    int n = bid >> 8;
    int tid = threadIdx.x, lane = tid & 31, wid = tid >> 5;
    int g = lane >> 2, t = lane & 3;
    int m0 = (wid >> 1) * 16;       // attention j-tile
    int half = wid & 1;
    int om0 = wid * 16;             // out o-tile

    uint32_t sq_a = (uint32_t)__cvta_generic_to_shared(sq);
    uint32_t sk_a = (uint32_t)__cvta_generic_to_shared(sk);
    uint32_t sv_a = (uint32_t)__cvta_generic_to_shared(sv);

    size_t winbase = ((size_t)n * HEADS) * WN + w;

    for (int i = tid; i < 7 * 132; i += 256) sv[49 * 132 + i] = 0.f;

    // prefetch head 0 q,k,v
    {
        const float4* gq4 = (const float4*)(g_q + winbase * (PT * DIM));
        const float4* gk4 = (const float4*)(g_k + winbase * (PT * DIM));
        const float4* gv4 = (const float4*)(g_v + winbase * (PT * DIM));
        for (int i = tid; i < PT * 32; i += 256) {
            int r = i >> 5, c = i & 31;
            uint32_t off = (uint32_t)(r * 132 + c * 4) * 4;
            cp16(sq_a + off, gq4 + i);
            cp16(sk_a + off, gk4 + i);
            cp16(sv_a + off, gv4 + i);
        }
        cp_commit();
    }

    float acc_o[7][4] = {};
    const float scale = 0.08838834764831845f;

    for (int h = 0; h < 8; h++) {
        asm volatile("cp.async.wait_group 0;");
        __syncthreads();

        // per-head bias table (read after next sync)
        for (int i = tid; i < 169; i += 256) sb[i] = pos_code[i * HEADS + h];

        size_t nextbase = winbase + (size_t)(h + 1) * WN;

        // ---- QK: S[j][i], m=64(j), n=56(i), k=128 ----
        {
            float acc[4][4] = {};
            #pragma unroll
            for (int ks = 0; ks < 16; ks++) {
                int k0 = ks * 8;
                uint32_t a[4];
                a[0] = __float_as_uint(sq[(m0 + g) * 132 + k0 + t]);
                a[1] = __float_as_uint(sq[(m0 + g + 8) * 132 + k0 + t]);
                a[2] = __float_as_uint(sq[(m0 + g) * 132 + k0 + t + 4]);
                a[3] = __float_as_uint(sq[(m0 + g + 8) * 132 + k0 + t + 4]);
                #pragma unroll
                for (int nt = 0; nt < 4; nt++) {
                    int nti = half * 4 + nt;
                    if (nti >= 7) break;
                    int n0 = nti * 8;
                    uint32_t b[2];
                    b[0] = __float_as_uint(sk[(n0 + g) * 132 + k0 + t]);
                    b[1] = __float_as_uint(sk[(n0 + g) * 132 + k0 + t + 4]);
                    mma_tf32(acc[nt], a, b);
                }
            }
            #pragma unroll
            for (int nt = 0; nt < 4; nt++) {
                int nti = half * 4 + nt;
                if (nti >= 7) break;
                int n0 = nti * 8;
                S[(m0 + g) * 60 + n0 + 2 * t]     = acc[nt][0];
                S[(m0 + g) * 60 + n0 + 2 * t + 1] = acc[nt][1];
                S[(m0 + g + 8) * 60 + n0 + 2 * t]     = acc[nt][2];
                S[(m0 + g + 8) * 60 + n0 + 2 * t + 1] = acc[nt][3];
            }
        }
        __syncthreads();

        // prefetch next k (sk free after QK)
        if (h < 7) {
            const float4* gk4 = (const float4*)(g_k + nextbase * (PT * DIM));
            for (int i = tid; i < PT * 32; i += 256) {
                int r = i >> 5, c = i & 31;
                cp16(sk_a + (uint32_t)(r * 132 + c * 4) * 4, gk4 + i);
            }
            cp_commit();
        }

        // ---- softmax over i per row j (scale + rel-pos bias), pad cols -> 0 ----
        for (int j = wid; j < PT; j += 8) {
            int yj = j / WIN, xj = j - yj * WIN;
            float* row = S + j * 60;
            int i0 = lane;
            int y0 = i0 / WIN, x0 = i0 - y0 * WIN;
            int r0 = (y0 - yj + WIN - 1) + (x0 - xj + WIN - 1) * (2 * WIN - 1);
            float v0 = row[i0] * scale + sb[r0];
            float v1 = -1e30f;
            int i1 = lane + 32;
            if (i1 < PT) {
                int y1 = i1 / WIN, x1 = i1 - y1 * WIN;
                int r1 = (y1 - yj + WIN - 1) + (x1 - xj + WIN - 1) * (2 * WIN - 1);
                v1 = row[i1] * scale + sb[r1];
            }
            float m = fmaxf(v0, v1);
            #pragma unroll
            for (int off = 16; off; off >>= 1) m = fmaxf(m, __shfl_xor_sync(0xffffffffu, m, off));
            float e0 = __expf(v0 - m);
            float e1 = (i1 < PT) ? __expf(v1 - m) : 0.f;
            float s = e0 + e1;
            #pragma unroll
            for (int off = 16; off; off >>= 1) s += __shfl_xor_sync(0xffffffffu, s, off);
            float inv = 1.f / s;
            row[i0] = tf32f(e0 * inv);
            if (i1 < PT) row[i1] = tf32f(e1 * inv);
            else if (i1 < 56) row[i1] = 0.f;
        }
        __syncthreads();

        // ---- PV: att[j][d] = P @ V; m=64(j), n=128(d), k=56 ----
        {
            float acc[8][4] = {};
            #pragma unroll
            for (int ks = 0; ks < 7; ks++) {
                int k0 = ks * 8;
                uint32_t a[4];
                a[0] = __float_as_uint(S[(m0 + g) * 60 + k0 + t]);
                a[1] = __float_as_uint(S[(m0 + g + 8) * 60 + k0 + t]);
                a[2] = __float_as_uint(S[(m0 + g) * 60 + k0 + t + 4]);
                a[3] = __float_as_uint(S[(m0 + g + 8) * 60 + k0 + t + 4]);
                #pragma unroll
                for (int nt = 0; nt < 8; nt++) {
                    int n0 = (half * 8 + nt) * 8;
                    uint32_t b[2];
                    b[0] = __float_as_uint(sv[(k0 + t) * 132 + n0 + g]);
                    b[1] = __float_as_uint(sv[(k0 + t + 4) * 132 + n0 + g]);
                    mma_tf32(acc[nt], a, b);
                }
            }
            #pragma unroll
            for (int nt = 0; nt < 8; nt++) {
                int d0 = (half * 8 + nt) * 8 + 2 * t;
                att[(m0 + g) * 132 + d0]         = tf32f(acc[nt][0]);
                att[(m0 + g) * 132 + d0 + 1]     = tf32f(acc[nt][1]);
                att[(m0 + g + 8) * 132 + d0]     = tf32f(acc[nt][2]);
                att[(m0 + g + 8) * 132 + d0 + 1] = tf32f(acc[nt][3]);
            }
        }
        __syncthreads();

        // prefetch next v (sv free after PV)
        if (h < 7) {
            const float4* gv4 = (const float4*)(g_v + nextbase * (PT * DIM));
            for (int i = tid; i < PT * 32; i += 256) {
                int r = i >> 5, c = i & 31;
                cp16(sv_a + (uint32_t)(r * 132 + c * 4) * 4, gv4 + i);
            }
            cp_commit();
        }

        // ---- out accumulate: C[o][tok] += Wo_h[o][d] @ att[tok][d]; Wo via LDG ----
        {
            const float* woh = g_woR + (size_t)om0 * (HEADS * DIM) + h * DIM;
            #pragma unroll
            for (int ks = 0; ks < 16; ks++) {
                int k0 = ks * 8;
                uint32_t a[4];
                a[0] = __float_as_uint(__ldg(&woh[(size_t)g * 1024 + k0 + t]));
                a[1] = __float_as_uint(__ldg(&woh[(size_t)(g + 8) * 1024 + k0 + t]));
                a[2] = __float_as_uint(__ldg(&woh[(size_t)g * 1024 + k0 + t + 4]));
                a[3] = __float_as_uint(__ldg(&woh[(size_t)(g + 8) * 1024 + k0 + t + 4]));
                #pragma unroll
                for (int nt = 0; nt < 7; nt++) {
                    uint32_t b[2];
                    b[0] = __float_as_uint(att[(nt * 8 + g) * 132 + k0 + t]);
                    b[1] = __float_as_uint(att[(nt * 8 + g) * 132 + k0 + t + 4]);
                    mma_tf32(acc_o[nt], a, b);
                }
            }
        }
        __syncthreads();

        // prefetch next q into sq (= att, reads done)
        if (h < 7) {
            const float4* gq4 = (const float4*)(g_q + nextbase * (PT * DIM));
            for (int i = tid; i < PT * 32; i += 256) {
                int r = i >> 5, c = i & 31;
                cp16(sq_a + (uint32_t)(r * 132 + c * 4) * 4, gq4 + i);
            }
            cp_commit();
        }
    }

    // ---- final store ----
    int wy = w >> 4, wx = w & 15;
    float* dst_n = out + (size_t)n * DIM * PPTS;
    #pragma unroll
    for (int rs = 0; rs < 2; rs++) {
        int o = om0 + g + rs * 8;
        float bias = bo[o];
        float* dst = dst_n + (size_t)o * PPTS;
        #pragma unroll
        for (int nt = 0; nt < 7; nt++) {
            #pragma unroll
            for (int cs = 0; cs < 2; cs++) {
                int tok = nt * 8 + 2 * t + cs;
                if (tok < PT) {
                    int jy = tok / WIN, jx = tok - jy * WIN;
                    int p = (wy * WIN + jy) * CWID + wx * WIN + jx;
                    dst[p] = acc_o[nt][rs * 2 + cs] + bias;
                }
            }
        }
    }
}

// ---------------- launch ----------------
extern "C" void kernel_launch(void* const* d_in, const int* in_sizes, int n_in,
                              void* d_out, int out_size) {
    const float* x   = (const float*)d_in[0];
    const float* Wq  = (const float*)d_in[1];
    const float* bq  = (const float*)d_in[2];
    const float* Wk  = (const float*)d_in[3];
    const float* bk  = (const float*)d_in[4];
    const float* Wv  = (const float*)d_in[5];
    const float* bv  = (const float*)d_in[6];
    const float* Wo  = (const float*)d_in[7];
    const float* bo  = (const float*)d_in[8];
    const float* pos = (const float*)d_in[9];
    float* out = (float*)d_out;

    wo_prep<<<128, 256>>>(Wo);
    {
        dim3 grid(PPTS / 128, HEADS, 12);
        qkv_kernel<<<grid, 256>>>(x, Wq, bq, Wk, bk, Wv, bv);
    }
    {
        const int smem = SM_FLOATS * (int)sizeof(float);   // ~109 KB -> 2 CTAs/SM
        static int attr_set = 0;
        if (!attr_set) {
            cudaFuncSetAttribute(attn_out_kernel, cudaFuncAttributeMaxDynamicSharedMemorySize, smem);
            attr_set = 1;
        }
        attn_out_kernel<<<NB * WN, 256, smem>>>(pos, bo, out);
    }
}

// round 7
// speedup vs baseline: 1.1230x; 1.0641x over previous
#include <cuda_runtime.h>
#include <cuda_bf16.h>
#include <cstdint>

// ---------------- problem constants ----------------
#define NB    4
#define DIM   128
#define HEADS 8
#define PPTS  12544
#define CWID  112
#define WIN   7
#define NWX   16
#define WN    256
#define PT    49

// q,k,v: [n][h][win][tok=49][d=128], values pre-rounded to tf32
__device__ float g_q[(size_t)NB * HEADS * WN * PT * DIM];
__device__ float g_k[(size_t)NB * HEADS * WN * PT * DIM];
__device__ float g_v[(size_t)NB * HEADS * WN * PT * DIM];
__device__ float g_woR[(size_t)DIM * HEADS * DIM];        // Wo rounded to tf32
__device__ float g_wR[(size_t)3 * HEADS * DIM * DIM];     // Wq/Wk/Wv rounded
__device__ float g_xR[(size_t)NB * DIM * PPTS];           // x rounded

__device__ __forceinline__ float tf32f(float x) {
    uint32_t u;
    asm("cvt.rna.tf32.f32 %0, %1;" : "=r"(u) : "f"(x));
    return __uint_as_float(u);
}

__device__ __forceinline__ void mma_tf32(float c[4], const uint32_t a[4], const uint32_t b[2]) {
    asm volatile(
        "mma.sync.aligned.m16n8k8.row.col.f32.tf32.tf32.f32 "
        "{%0,%1,%2,%3}, {%4,%5,%6,%7}, {%8,%9}, {%0,%1,%2,%3};\n"
        : "+f"(c[0]), "+f"(c[1]), "+f"(c[2]), "+f"(c[3])
        : "r"(a[0]), "r"(a[1]), "r"(a[2]), "r"(a[3]), "r"(b[0]), "r"(b[1]));
}

__device__ __forceinline__ void cp16(uint32_t smem_addr, const void* gptr) {
    asm volatile("cp.async.cg.shared.global [%0], [%1], 16;" :: "r"(smem_addr), "l"(gptr));
}
__device__ __forceinline__ void cp_commit() {
    asm volatile("cp.async.commit_group;");
}

// ---------------- prep kernels: round weights / x to tf32 ----------------
__global__ void wo_prep(const float* __restrict__ Wo) {
    int i = blockIdx.x * 256 + threadIdx.x;     // 32768 float4
    float4 v = ((const float4*)Wo)[i];
    ((float4*)g_woR)[i] = make_float4(tf32f(v.x), tf32f(v.y), tf32f(v.z), tf32f(v.w));
}
__global__ void w_prep(const float* __restrict__ Wq, const float* __restrict__ Wk,
                       const float* __restrict__ Wv) {
    int i = blockIdx.x * 256 + threadIdx.x;     // 32768 float4 per matrix
    const float* src = (blockIdx.y == 0) ? Wq : (blockIdx.y == 1) ? Wk : Wv;
    float4 v = ((const float4*)src)[i];
    ((float4*)g_wR)[(size_t)blockIdx.y * 32768 + i] =
        make_float4(tf32f(v.x), tf32f(v.y), tf32f(v.z), tf32f(v.w));
}
__global__ void x_prep(const float* __restrict__ x) {
    size_t i = (size_t)blockIdx.x * 256 + threadIdx.x;   // 1,605,632 float4
    float4 v = ((const float4*)x)[i];
    ((float4*)g_xR)[i] = make_float4(tf32f(v.x), tf32f(v.y), tf32f(v.z), tf32f(v.w));
}

// ---------------- Kernel A: QKV projection, cp.async pipelined ----------------
// smem: As [128][132] @0 ; Bs [2][32][136] @16896 ; total 25600 floats (100 KB)
#define QA_OFF 0
#define QB_OFF 16896
#define Q_SM_FLOATS 25600

__global__ __launch_bounds__(256, 2)
void qkv_kernel(const float* __restrict__ bq, const float* __restrict__ bk,
                const float* __restrict__ bv) {
    extern __shared__ float qsm[];
    float* As = qsm + QA_OFF;                 // [o][k] stride 132
    float* Bs = qsm + QB_OFF;                 // [st][k][p] stride 136

    int z = blockIdx.z;
    int n = z & 3;
    int which = z >> 2;
    const float* bvec = (which == 0) ? bq : (which == 1) ? bk : bv;
    float* garr = (which == 0) ? g_q : (which == 1) ? g_k : g_v;
    int h = blockIdx.y;
    int p_base = blockIdx.x * 128;
    const float* Wsrc = g_wR + (size_t)which * 131072 + (size_t)h * 128 * 128;
    const float* xn = g_xR + (size_t)n * DIM * PPTS;

    int tid = threadIdx.x, lane = tid & 31, wid = tid >> 5;
    int g = lane >> 2, t = lane & 3;
    int m0w = (wid >> 2) * 64, n0w = (wid & 3) * 32;

    uint32_t As_a = (uint32_t)__cvta_generic_to_shared(As);
    uint32_t Bs_a = (uint32_t)__cvta_generic_to_shared(Bs);

    // issue full-A copy + B stage 0, one group
    #pragma unroll
    for (int r = 0; r < 16; r++) {
        int i = tid + r * 256;                // 4096 chunks
        int row = i >> 5, c = i & 31;
        cp16(As_a + (uint32_t)(row * 132 + c * 4) * 4, Wsrc + (size_t)row * 128 + c * 4);
    }
    #pragma unroll
    for (int r = 0; r < 4; r++) {
        int i = tid + r * 256;                // 1024 chunks
        int kk = i >> 5, c = i & 31;
        cp16(Bs_a + (uint32_t)(kk * 136 + c * 4) * 4, xn + (size_t)kk * PPTS + p_base + c * 4);
    }
    cp_commit();

    float acc[4][4][4] = {};

    #pragma unroll
    for (int it = 0; it < 4; it++) {
        int st = it & 1;
        if (it < 3) {
            int nst = (it + 1) & 1;
            int k0n = (it + 1) * 32;
            #pragma unroll
            for (int r = 0; r < 4; r++) {
                int i = tid + r * 256;
                int kk = i >> 5, c = i & 31;
                cp16(Bs_a + (uint32_t)(nst * 32 * 136 + kk * 136 + c * 4) * 4,
                     xn + (size_t)(k0n + kk) * PPTS + p_base + c * 4);
            }
            cp_commit();
            asm volatile("cp.async.wait_group 1;");
        } else {
            asm volatile("cp.async.wait_group 0;");
        }
        __syncthreads();

        const float* Bst = Bs + st * (32 * 136);
        #pragma unroll
        for (int ks = 0; ks < 4; ks++) {
            int k0 = ks * 8;
            uint32_t af[4][4], bf[4][2];
            #pragma unroll
            for (int mf = 0; mf < 4; mf++) {
                int m = m0w + mf * 16;
                af[mf][0] = __float_as_uint(As[(m + g) * 132 + it * 32 + k0 + t]);
                af[mf][1] = __float_as_uint(As[(m + g + 8) * 132 + it * 32 + k0 + t]);
                af[mf][2] = __float_as_uint(As[(m + g) * 132 + it * 32 + k0 + t + 4]);
                af[mf][3] = __float_as_uint(As[(m + g + 8) * 132 + it * 32 + k0 + t + 4]);
            }
            #pragma unroll
            for (int nf = 0; nf < 4; nf++) {
                int nn = n0w + nf * 8 + g;
                bf[nf][0] = __float_as_uint(Bst[(k0 + t) * 136 + nn]);
                bf[nf][1] = __float_as_uint(Bst[(k0 + t + 4) * 136 + nn]);
            }
            #pragma unroll
            for (int mf = 0; mf < 4; mf++)
                #pragma unroll
                for (int nf = 0; nf < 4; nf++)
                    mma_tf32(acc[mf][nf], af[mf], bf[nf]);
        }
        __syncthreads();
    }

    float biasr[4][2];
    #pragma unroll
    for (int mf = 0; mf < 4; mf++)
        #pragma unroll
        for (int rs = 0; rs < 2; rs++)
            biasr[mf][rs] = bvec[h * 128 + m0w + mf * 16 + rs * 8 + g];

    size_t headbase = ((size_t)n * HEADS + h) * WN;

    #pragma unroll
    for (int nf = 0; nf < 4; nf++) {
        #pragma unroll
        for (int cs = 0; cs < 2; cs++) {
            int p = p_base + n0w + nf * 8 + 2 * t + cs;
            int pr = p / CWID, pc = p - pr * CWID;
            int win = (pr / WIN) * NWX + (pc / WIN);
            int tok = (pr % WIN) * WIN + (pc % WIN);
            float* base = garr + ((headbase + win) * PT + tok) * DIM;
            #pragma unroll
            for (int mf = 0; mf < 4; mf++)
                #pragma unroll
                for (int rs = 0; rs < 2; rs++) {
                    int d = m0w + mf * 16 + rs * 8 + g;
                    base[d] = tf32f(acc[mf][nf][rs * 2 + cs] + biasr[mf][rs]);
                }
        }
    }
}

// ---------------- Kernel B: fused attention + output projection ----------------
#define SQ_OFF  0          // sq/att [64][132]  (aliased)
#define SK_OFF  8448       // sk  [56][132]
#define SV_OFF  15840      // sv  [56][132] (rows 49..55 zeroed once)
#define SS_OFF  23232      // S   [64][60]
#define SB_OFF  27072      // sb  [176]
#define SM_FLOATS 27248    // 108,992 B

__global__ __launch_bounds__(256, 2)
void attn_out_kernel(const float* __restrict__ pos_code,
                     const float* __restrict__ bo,
                     float* __restrict__ out) {
    extern __shared__ float sm[];
    float* sq  = sm + SQ_OFF;
    float* sk  = sm + SK_OFF;
    float* sv  = sm + SV_OFF;
    float* att = sm + SQ_OFF;       // alias: q dead after QK
    float* S   = sm + SS_OFF;
    float* sb  = sm + SB_OFF;

    int bid = blockIdx.x;
    int w = bid & 255;
    int n = bid >> 8;
    int tid = threadIdx.x, lane = tid & 31, wid = tid >> 5;
    int g = lane >> 2, t = lane & 3;
    int m0 = (wid >> 1) * 16;
    int half = wid & 1;
    int om0 = wid * 16;

    uint32_t sq_a = (uint32_t)__cvta_generic_to_shared(sq);
    uint32_t sk_a = (uint32_t)__cvta_generic_to_shared(sk);
    uint32_t sv_a = (uint32_t)__cvta_generic_to_shared(sv);

    size_t winbase = ((size_t)n * HEADS) * WN + w;

    for (int i = tid; i < 7 * 132; i += 256) sv[49 * 132 + i] = 0.f;

    {
        const float4* gq4 = (const float4*)(g_q + winbase * (PT * DIM));
        const float4* gk4 = (const float4*)(g_k + winbase * (PT * DIM));
        const float4* gv4 = (const float4*)(g_v + winbase * (PT * DIM));
        for (int i = tid; i < PT * 32; i += 256) {
            int r = i >> 5, c = i & 31;
            uint32_t off = (uint32_t)(r * 132 + c * 4) * 4;
            cp16(sq_a + off, gq4 + i);
            cp16(sk_a + off, gk4 + i);
            cp16(sv_a + off, gv4 + i);
        }
        cp_commit();
    }

    float acc_o[7][4] = {};
    const float scale = 0.08838834764831845f;

    for (int h = 0; h < 8; h++) {
        asm volatile("cp.async.wait_group 0;");
        __syncthreads();

        for (int i = tid; i < 169; i += 256) sb[i] = pos_code[i * HEADS + h];

        size_t nextbase = winbase + (size_t)(h + 1) * WN;

        // ---- QK ----
        {
            float acc[4][4] = {};
            #pragma unroll
            for (int ks = 0; ks < 16; ks++) {
                int k0 = ks * 8;
                uint32_t a[4];
                a[0] = __float_as_uint(sq[(m0 + g) * 132 + k0 + t]);
                a[1] = __float_as_uint(sq[(m0 + g + 8) * 132 + k0 + t]);
                a[2] = __float_as_uint(sq[(m0 + g) * 132 + k0 + t + 4]);
                a[3] = __float_as_uint(sq[(m0 + g + 8) * 132 + k0 + t + 4]);
                #pragma unroll
                for (int nt = 0; nt < 4; nt++) {
                    int nti = half * 4 + nt;
                    if (nti >= 7) break;
                    int n0 = nti * 8;
                    uint32_t b[2];
                    b[0] = __float_as_uint(sk[(n0 + g) * 132 + k0 + t]);
                    b[1] = __float_as_uint(sk[(n0 + g) * 132 + k0 + t + 4]);
                    mma_tf32(acc[nt], a, b);
                }
            }
            #pragma unroll
            for (int nt = 0; nt < 4; nt++) {
                int nti = half * 4 + nt;
                if (nti >= 7) break;
                int n0 = nti * 8;
                S[(m0 + g) * 60 + n0 + 2 * t]     = acc[nt][0];
                S[(m0 + g) * 60 + n0 + 2 * t + 1] = acc[nt][1];
                S[(m0 + g + 8) * 60 + n0 + 2 * t]     = acc[nt][2];
                S[(m0 + g + 8) * 60 + n0 + 2 * t + 1] = acc[nt][3];
            }
        }
        __syncthreads();

        if (h < 7) {
            const float4* gk4 = (const float4*)(g_k + nextbase * (PT * DIM));
            for (int i = tid; i < PT * 32; i += 256) {
                int r = i >> 5, c = i & 31;
                cp16(sk_a + (uint32_t)(r * 132 + c * 4) * 4, gk4 + i);
            }
            cp_commit();
        }

        // ---- softmax ----
        for (int j = wid; j < PT; j += 8) {
            int yj = j / WIN, xj = j - yj * WIN;
            float* row = S + j * 60;
            int i0 = lane;
            int y0 = i0 / WIN, x0 = i0 - y0 * WIN;
            int r0 = (y0 - yj + WIN - 1) + (x0 - xj + WIN - 1) * (2 * WIN - 1);
            float v0 = row[i0] * scale + sb[r0];
            float v1 = -1e30f;
            int i1 = lane + 32;
            if (i1 < PT) {
                int y1 = i1 / WIN, x1 = i1 - y1 * WIN;
                int r1 = (y1 - yj + WIN - 1) + (x1 - xj + WIN - 1) * (2 * WIN - 1);
                v1 = row[i1] * scale + sb[r1];
            }
            float m = fmaxf(v0, v1);
            #pragma unroll
            for (int off = 16; off; off >>= 1) m = fmaxf(m, __shfl_xor_sync(0xffffffffu, m, off));
            float e0 = __expf(v0 - m);
            float e1 = (i1 < PT) ? __expf(v1 - m) : 0.f;
            float s = e0 + e1;
            #pragma unroll
            for (int off = 16; off; off >>= 1) s += __shfl_xor_sync(0xffffffffu, s, off);
            float inv = 1.f / s;
            row[i0] = tf32f(e0 * inv);
            if (i1 < PT) row[i1] = tf32f(e1 * inv);
            else if (i1 < 56) row[i1] = 0.f;
        }
        __syncthreads();

        // ---- PV ----
        {
            float acc[8][4] = {};
            #pragma unroll
            for (int ks = 0; ks < 7; ks++) {
                int k0 = ks * 8;
                uint32_t a[4];
                a[0] = __float_as_uint(S[(m0 + g) * 60 + k0 + t]);
                a[1] = __float_as_uint(S[(m0 + g + 8) * 60 + k0 + t]);
                a[2] = __float_as_uint(S[(m0 + g) * 60 + k0 + t + 4]);
                a[3] = __float_as_uint(S[(m0 + g + 8) * 60 + k0 + t + 4]);
                #pragma unroll
                for (int nt = 0; nt < 8; nt++) {
                    int n0 = (half * 8 + nt) * 8;
                    uint32_t b[2];
                    b[0] = __float_as_uint(sv[(k0 + t) * 132 + n0 + g]);
                    b[1] = __float_as_uint(sv[(k0 + t + 4) * 132 + n0 + g]);
                    mma_tf32(acc[nt], a, b);
                }
            }
            #pragma unroll
            for (int nt = 0; nt < 8; nt++) {
                int d0 = (half * 8 + nt) * 8 + 2 * t;
                att[(m0 + g) * 132 + d0]         = tf32f(acc[nt][0]);
                att[(m0 + g) * 132 + d0 + 1]     = tf32f(acc[nt][1]);
                att[(m0 + g + 8) * 132 + d0]     = tf32f(acc[nt][2]);
                att[(m0 + g + 8) * 132 + d0 + 1] = tf32f(acc[nt][3]);
            }
        }
        __syncthreads();

        if (h < 7) {
            const float4* gv4 = (const float4*)(g_v + nextbase * (PT * DIM));
            for (int i = tid; i < PT * 32; i += 256) {
                int r = i >> 5, c = i & 31;
                cp16(sv_a + (uint32_t)(r * 132 + c * 4) * 4, gv4 + i);
            }
            cp_commit();
        }

        // ---- out accumulate ----
        {
            const float* woh = g_woR + (size_t)om0 * (HEADS * DIM) + h * DIM;
            #pragma unroll
            for (int ks = 0; ks < 16; ks++) {
                int k0 = ks * 8;
                uint32_t a[4];
                a[0] = __float_as_uint(__ldg(&woh[(size_t)g * 1024 + k0 + t]));
                a[1] = __float_as_uint(__ldg(&woh[(size_t)(g + 8) * 1024 + k0 + t]));
                a[2] = __float_as_uint(__ldg(&woh[(size_t)g * 1024 + k0 + t + 4]));
                a[3] = __float_as_uint(__ldg(&woh[(size_t)(g + 8) * 1024 + k0 + t + 4]));
                #pragma unroll
                for (int nt = 0; nt < 7; nt++) {
                    uint32_t b[2];
                    b[0] = __float_as_uint(att[(nt * 8 + g) * 132 + k0 + t]);
                    b[1] = __float_as_uint(att[(nt * 8 + g) * 132 + k0 + t + 4]);
                    mma_tf32(acc_o[nt], a, b);
                }
            }
        }
        __syncthreads();

        if (h < 7) {
            const float4* gq4 = (const float4*)(g_q + nextbase * (PT * DIM));
            for (int i = tid; i < PT * 32; i += 256) {
                int r = i >> 5, c = i & 31;
                cp16(sq_a + (uint32_t)(r * 132 + c * 4) * 4, gq4 + i);
            }
            cp_commit();
        }
    }

    // ---- final store ----
    int wy = w >> 4, wx = w & 15;
    float* dst_n = out + (size_t)n * DIM * PPTS;
    #pragma unroll
    for (int rs = 0; rs < 2; rs++) {
        int o = om0 + g + rs * 8;
        float bias = bo[o];
        float* dst = dst_n + (size_t)o * PPTS;
        #pragma unroll
        for (int nt = 0; nt < 7; nt++) {
            #pragma unroll
            for (int cs = 0; cs < 2; cs++) {
                int tok = nt * 8 + 2 * t + cs;
                if (tok < PT) {
                    int jy = tok / WIN, jx = tok - jy * WIN;
                    int p = (wy * WIN + jy) * CWID + wx * WIN + jx;
                    dst[p] = acc_o[nt][rs * 2 + cs] + bias;
                }
            }
        }
    }
}

// ---------------- launch ----------------
extern "C" void kernel_launch(void* const* d_in, const int* in_sizes, int n_in,
                              void* d_out, int out_size) {
    const float* x   = (const float*)d_in[0];
    const float* Wq  = (const float*)d_in[1];
    const float* bq  = (const float*)d_in[2];
    const float* Wk  = (const float*)d_in[3];
    const float* bk  = (const float*)d_in[4];
    const float* Wv  = (const float*)d_in[5];
    const float* bv  = (const float*)d_in[6];
    const float* Wo  = (const float*)d_in[7];
    const float* bo  = (const float*)d_in[8];
    const float* pos = (const float*)d_in[9];
    float* out = (float*)d_out;

    wo_prep<<<128, 256>>>(Wo);
    {
        dim3 gw(128, 3);
        w_prep<<<gw, 256>>>(Wq, Wk, Wv);
    }
    x_prep<<<6272, 256>>>(x);

    {
        static int attr_set = 0;
        if (!attr_set) {
            cudaFuncSetAttribute(qkv_kernel, cudaFuncAttributeMaxDynamicSharedMemorySize,
                                 Q_SM_FLOATS * (int)sizeof(float));
            cudaFuncSetAttribute(attn_out_kernel, cudaFuncAttributeMaxDynamicSharedMemorySize,
                                 SM_FLOATS * (int)sizeof(float));
            attr_set = 1;
        }
    }
    {
        dim3 grid(PPTS / 128, HEADS, 12);
        qkv_kernel<<<grid, 256, Q_SM_FLOATS * sizeof(float)>>>(bq, bk, bv);
    }
    attn_out_kernel<<<NB * WN, 256, SM_FLOATS * sizeof(float)>>>(pos, bo, out);
}

// round 8
// speedup vs baseline: 1.3021x; 1.1594x over previous
#include <cuda_runtime.h>
#include <cuda_bf16.h>
#include <cstdint>

// ---------------- problem constants ----------------
#define NB    4
#define DIM   128
#define HEADS 8
#define PPTS  12544
#define CWID  112
#define WIN   7
#define NWX   16
#define WN    256
#define PT    49

// q,k,v: [n][h][win][tok=49][d=128], values pre-rounded to tf32
__device__ float g_q[(size_t)NB * HEADS * WN * PT * DIM];
__device__ float g_k[(size_t)NB * HEADS * WN * PT * DIM];
__device__ float g_v[(size_t)NB * HEADS * WN * PT * DIM];
__device__ float g_woF[(size_t)DIM * HEADS * DIM];        // Wo, fragment-major, tf32
__device__ float g_wR[(size_t)3 * HEADS * DIM * DIM];     // Wq/Wk/Wv rounded
__device__ float g_xR[(size_t)NB * DIM * PPTS];           // x rounded

__device__ __forceinline__ float tf32f(float x) {
    uint32_t u;
    asm("cvt.rna.tf32.f32 %0, %1;" : "=r"(u) : "f"(x));
    return __uint_as_float(u);
}

__device__ __forceinline__ void mma_tf32(float c[4], const uint32_t a[4], const uint32_t b[2]) {
    asm volatile(
        "mma.sync.aligned.m16n8k8.row.col.f32.tf32.tf32.f32 "
        "{%0,%1,%2,%3}, {%4,%5,%6,%7}, {%8,%9}, {%0,%1,%2,%3};\n"
        : "+f"(c[0]), "+f"(c[1]), "+f"(c[2]), "+f"(c[3])
        : "r"(a[0]), "r"(a[1]), "r"(a[2]), "r"(a[3]), "r"(b[0]), "r"(b[1]));
}

__device__ __forceinline__ void cp16(uint32_t smem_addr, const void* gptr) {
    asm volatile("cp.async.cg.shared.global [%0], [%1], 16;" :: "r"(smem_addr), "l"(gptr));
}
__device__ __forceinline__ void cp_commit() {
    asm volatile("cp.async.commit_group;");
}

// ---------------- prep kernels ----------------
// Wo -> fragment-major: float4 per (wid, h, ks, lane)
__global__ void wo_frag_prep(const float* __restrict__ Wo) {
    int idx = blockIdx.x * 256 + threadIdx.x;       // 131072 total
    int lane = idx & 31;
    int ks   = (idx >> 5) & 15;
    int h    = (idx >> 9) & 7;
    int wd   = idx >> 12;                           // 0..7
    int g = lane >> 2, t = lane & 3;
    int row = wd * 16 + g;
    int col = h * 128 + ks * 8 + t;
    float4 v;
    v.x = tf32f(Wo[(size_t)row * 1024 + col]);
    v.y = tf32f(Wo[(size_t)(row + 8) * 1024 + col]);
    v.z = tf32f(Wo[(size_t)row * 1024 + col + 4]);
    v.w = tf32f(Wo[(size_t)(row + 8) * 1024 + col + 4]);
    ((float4*)g_woF)[idx] = v;
}
__global__ void w_prep(const float* __restrict__ Wq, const float* __restrict__ Wk,
                       const float* __restrict__ Wv) {
    int i = blockIdx.x * 256 + threadIdx.x;     // 32768 float4 per matrix
    const float* src = (blockIdx.y == 0) ? Wq : (blockIdx.y == 1) ? Wk : Wv;
    float4 v = ((const float4*)src)[i];
    ((float4*)g_wR)[(size_t)blockIdx.y * 32768 + i] =
        make_float4(tf32f(v.x), tf32f(v.y), tf32f(v.z), tf32f(v.w));
}
__global__ void x_prep(const float* __restrict__ x) {
    size_t i = (size_t)blockIdx.x * 256 + threadIdx.x;   // 1,605,632 float4
    float4 v = ((const float4*)x)[i];
    ((float4*)g_xR)[i] = make_float4(tf32f(v.x), tf32f(v.y), tf32f(v.z), tf32f(v.w));
}

// ---------------- Kernel A: QKV projection, 4 warps, warp tile 64x64 ----------------
// smem: As [128][132] @0 ; Bs [2][32][136] @16896 ; total 25600 floats (102.4 KB)
#define QA_OFF 0
#define QB_OFF 16896
#define Q_SM_FLOATS 25600

__global__ __launch_bounds__(128, 2)
void qkv_kernel(const float* __restrict__ bq, const float* __restrict__ bk,
                const float* __restrict__ bv) {
    extern __shared__ float qsm[];
    float* As = qsm + QA_OFF;                 // [o][k] stride 132
    float* Bs = qsm + QB_OFF;                 // [st][k][p] stride 136

    int z = blockIdx.z;
    int n = z & 3;
    int which = z >> 2;
    const float* bvec = (which == 0) ? bq : (which == 1) ? bk : bv;
    float* garr = (which == 0) ? g_q : (which == 1) ? g_k : g_v;
    int h = blockIdx.y;
    int p_base = blockIdx.x * 128;
    const float* Wsrc = g_wR + (size_t)which * 131072 + (size_t)h * 128 * 128;
    const float* xn = g_xR + (size_t)n * DIM * PPTS;

    int tid = threadIdx.x, lane = tid & 31, wid = tid >> 5;   // 4 warps
    int g = lane >> 2, t = lane & 3;
    int m0w = (wid >> 1) * 64, n0w = (wid & 1) * 64;

    uint32_t As_a = (uint32_t)__cvta_generic_to_shared(As);
    uint32_t Bs_a = (uint32_t)__cvta_generic_to_shared(Bs);

    // full-A copy + B stage 0
    #pragma unroll
    for (int r = 0; r < 32; r++) {
        int i = tid + r * 128;                // 4096 chunks
        int row = i >> 5, c = i & 31;
        cp16(As_a + (uint32_t)(row * 132 + c * 4) * 4, Wsrc + (size_t)row * 128 + c * 4);
    }
    #pragma unroll
    for (int r = 0; r < 8; r++) {
        int i = tid + r * 128;                // 1024 chunks
        int kk = i >> 5, c = i & 31;
        cp16(Bs_a + (uint32_t)(kk * 136 + c * 4) * 4, xn + (size_t)kk * PPTS + p_base + c * 4);
    }
    cp_commit();

    float acc[4][8][4] = {};

    #pragma unroll
    for (int it = 0; it < 4; it++) {
        int st = it & 1;
        if (it < 3) {
            int nst = (it + 1) & 1;
            int k0n = (it + 1) * 32;
            #pragma unroll
            for (int r = 0; r < 8; r++) {
                int i = tid + r * 128;
                int kk = i >> 5, c = i & 31;
                cp16(Bs_a + (uint32_t)(nst * 32 * 136 + kk * 136 + c * 4) * 4,
                     xn + (size_t)(k0n + kk) * PPTS + p_base + c * 4);
            }
            cp_commit();
            asm volatile("cp.async.wait_group 1;");
        } else {
            asm volatile("cp.async.wait_group 0;");
        }
        __syncthreads();

        const float* Bst = Bs + st * (32 * 136);
        #pragma unroll
        for (int ks = 0; ks < 4; ks++) {
            int k0 = ks * 8;
            uint32_t af[4][4], bf[8][2];
            #pragma unroll
            for (int mf = 0; mf < 4; mf++) {
                int m = m0w + mf * 16;
                af[mf][0] = __float_as_uint(As[(m + g) * 132 + it * 32 + k0 + t]);
                af[mf][1] = __float_as_uint(As[(m + g + 8) * 132 + it * 32 + k0 + t]);
                af[mf][2] = __float_as_uint(As[(m + g) * 132 + it * 32 + k0 + t + 4]);
                af[mf][3] = __float_as_uint(As[(m + g + 8) * 132 + it * 32 + k0 + t + 4]);
            }
            #pragma unroll
            for (int nf = 0; nf < 8; nf++) {
                int nn = n0w + nf * 8 + g;
                bf[nf][0] = __float_as_uint(Bst[(k0 + t) * 136 + nn]);
                bf[nf][1] = __float_as_uint(Bst[(k0 + t + 4) * 136 + nn]);
            }
            #pragma unroll
            for (int mf = 0; mf < 4; mf++)
                #pragma unroll
                for (int nf = 0; nf < 8; nf++)
                    mma_tf32(acc[mf][nf], af[mf], bf[nf]);
        }
        __syncthreads();
    }

    float biasr[4][2];
    #pragma unroll
    for (int mf = 0; mf < 4; mf++)
        #pragma unroll
        for (int rs = 0; rs < 2; rs++)
            biasr[mf][rs] = bvec[h * 128 + m0w + mf * 16 + rs * 8 + g];

    size_t headbase = ((size_t)n * HEADS + h) * WN;

    #pragma unroll
    for (int nf = 0; nf < 8; nf++) {
        #pragma unroll
        for (int cs = 0; cs < 2; cs++) {
            int p = p_base + n0w + nf * 8 + 2 * t + cs;
            int pr = p / CWID, pc = p - pr * CWID;
            int win = (pr / WIN) * NWX + (pc / WIN);
            int tok = (pr % WIN) * WIN + (pc % WIN);
            float* base = garr + ((headbase + win) * PT + tok) * DIM;
            #pragma unroll
            for (int mf = 0; mf < 4; mf++)
                #pragma unroll
                for (int rs = 0; rs < 2; rs++) {
                    int d = m0w + mf * 16 + rs * 8 + g;
                    base[d] = tf32f(acc[mf][nf][rs * 2 + cs] + biasr[mf][rs]);
                }
        }
    }
}

// ---------------- Kernel B: fused attention + output projection ----------------
#define SQ_OFF  0          // sq/att [64][132]  (aliased)
#define SK_OFF  8448       // sk  [56][132]
#define SV_OFF  15840      // sv  [56][132] (rows 49..55 zeroed once)
#define SS_OFF  23232      // S   [64][60]
#define SB_OFF  27072      // sb  [176]
#define SM_FLOATS 27248    // 108,992 B

__global__ __launch_bounds__(256, 2)
void attn_out_kernel(const float* __restrict__ pos_code,
                     const float* __restrict__ bo,
                     float* __restrict__ out) {
    extern __shared__ float sm[];
    float* sq  = sm + SQ_OFF;
    float* sk  = sm + SK_OFF;
    float* sv  = sm + SV_OFF;
    float* att = sm + SQ_OFF;       // alias: q dead after QK
    float* S   = sm + SS_OFF;
    float* sb  = sm + SB_OFF;

    int bid = blockIdx.x;
    int w = bid & 255;
    int n = bid >> 8;
    int tid = threadIdx.x, lane = tid & 31, wid = tid >> 5;
    int g = lane >> 2, t = lane & 3;
    int m0 = (wid >> 1) * 16;
    int half = wid & 1;
    int om0 = wid * 16;

    uint32_t sq_a = (uint32_t)__cvta_generic_to_shared(sq);
    uint32_t sk_a = (uint32_t)__cvta_generic_to_shared(sk);
    uint32_t sv_a = (uint32_t)__cvta_generic_to_shared(sv);

    size_t winbase = ((size_t)n * HEADS) * WN + w;

    for (int i = tid; i < 7 * 132; i += 256) sv[49 * 132 + i] = 0.f;

    {
        const float4* gq4 = (const float4*)(g_q + winbase * (PT * DIM));
        const float4* gk4 = (const float4*)(g_k + winbase * (PT * DIM));
        const float4* gv4 = (const float4*)(g_v + winbase * (PT * DIM));
        for (int i = tid; i < PT * 32; i += 256) {
            int r = i >> 5, c = i & 31;
            uint32_t off = (uint32_t)(r * 132 + c * 4) * 4;
            cp16(sq_a + off, gq4 + i);
            cp16(sk_a + off, gk4 + i);
            cp16(sv_a + off, gv4 + i);
        }
        cp_commit();
    }

    float acc_o[7][4] = {};
    const float scale = 0.08838834764831845f;

    for (int h = 0; h < 8; h++) {
        asm volatile("cp.async.wait_group 0;");
        __syncthreads();

        for (int i = tid; i < 169; i += 256) sb[i] = pos_code[i * HEADS + h];

        size_t nextbase = winbase + (size_t)(h + 1) * WN;

        // ---- QK ----
        {
            float acc[4][4] = {};
            #pragma unroll
            for (int ks = 0; ks < 16; ks++) {
                int k0 = ks * 8;
                uint32_t a[4];
                a[0] = __float_as_uint(sq[(m0 + g) * 132 + k0 + t]);
                a[1] = __float_as_uint(sq[(m0 + g + 8) * 132 + k0 + t]);
                a[2] = __float_as_uint(sq[(m0 + g) * 132 + k0 + t + 4]);
                a[3] = __float_as_uint(sq[(m0 + g + 8) * 132 + k0 + t + 4]);
                #pragma unroll
                for (int nt = 0; nt < 4; nt++) {
                    int nti = half * 4 + nt;
                    if (nti >= 7) break;
                    int n0 = nti * 8;
                    uint32_t b[2];
                    b[0] = __float_as_uint(sk[(n0 + g) * 132 + k0 + t]);
                    b[1] = __float_as_uint(sk[(n0 + g) * 132 + k0 + t + 4]);
                    mma_tf32(acc[nt], a, b);
                }
            }
            #pragma unroll
            for (int nt = 0; nt < 4; nt++) {
                int nti = half * 4 + nt;
                if (nti >= 7) break;
                int n0 = nti * 8;
                S[(m0 + g) * 60 + n0 + 2 * t]     = acc[nt][0];
                S[(m0 + g) * 60 + n0 + 2 * t + 1] = acc[nt][1];
                S[(m0 + g + 8) * 60 + n0 + 2 * t]     = acc[nt][2];
                S[(m0 + g + 8) * 60 + n0 + 2 * t + 1] = acc[nt][3];
            }
        }
        __syncthreads();

        if (h < 7) {
            const float4* gk4 = (const float4*)(g_k + nextbase * (PT * DIM));
            for (int i = tid; i < PT * 32; i += 256) {
                int r = i >> 5, c = i & 31;
                cp16(sk_a + (uint32_t)(r * 132 + c * 4) * 4, gk4 + i);
            }
            cp_commit();
        }

        // ---- softmax ----
        for (int j = wid; j < PT; j += 8) {
            int yj = j / WIN, xj = j - yj * WIN;
            float* row = S + j * 60;
            int i0 = lane;
            int y0 = i0 / WIN, x0 = i0 - y0 * WIN;
            int r0 = (y0 - yj + WIN - 1) + (x0 - xj + WIN - 1) * (2 * WIN - 1);
            float v0 = row[i0] * scale + sb[r0];
            float v1 = -1e30f;
            int i1 = lane + 32;
            if (i1 < PT) {
                int y1 = i1 / WIN, x1 = i1 - y1 * WIN;
                int r1 = (y1 - yj + WIN - 1) + (x1 - xj + WIN - 1) * (2 * WIN - 1);
                v1 = row[i1] * scale + sb[r1];
            }
            float m = fmaxf(v0, v1);
            #pragma unroll
            for (int off = 16; off; off >>= 1) m = fmaxf(m, __shfl_xor_sync(0xffffffffu, m, off));
            float e0 = __expf(v0 - m);
            float e1 = (i1 < PT) ? __expf(v1 - m) : 0.f;
            float s = e0 + e1;
            #pragma unroll
            for (int off = 16; off; off >>= 1) s += __shfl_xor_sync(0xffffffffu, s, off);
            float inv = 1.f / s;
            row[i0] = tf32f(e0 * inv);
            if (i1 < PT) row[i1] = tf32f(e1 * inv);
            else if (i1 < 56) row[i1] = 0.f;
        }
        __syncthreads();

        // ---- PV ----
        {
            float acc[8][4] = {};
            #pragma unroll
            for (int ks = 0; ks < 7; ks++) {
                int k0 = ks * 8;
                uint32_t a[4];
                a[0] = __float_as_uint(S[(m0 + g) * 60 + k0 + t]);
                a[1] = __float_as_uint(S[(m0 + g + 8) * 60 + k0 + t]);
                a[2] = __float_as_uint(S[(m0 + g) * 60 + k0 + t + 4]);
                a[3] = __float_as_uint(S[(m0 + g + 8) * 60 + k0 + t + 4]);
                #pragma unroll
                for (int nt = 0; nt < 8; nt++) {
                    int n0 = (half * 8 + nt) * 8;
                    uint32_t b[2];
                    b[0] = __float_as_uint(sv[(k0 + t) * 132 + n0 + g]);
                    b[1] = __float_as_uint(sv[(k0 + t + 4) * 132 + n0 + g]);
                    mma_tf32(acc[nt], a, b);
                }
            }
            #pragma unroll
            for (int nt = 0; nt < 8; nt++) {
                int d0 = (half * 8 + nt) * 8 + 2 * t;
                att[(m0 + g) * 132 + d0]         = tf32f(acc[nt][0]);
                att[(m0 + g) * 132 + d0 + 1]     = tf32f(acc[nt][1]);
                att[(m0 + g + 8) * 132 + d0]     = tf32f(acc[nt][2]);
                att[(m0 + g + 8) * 132 + d0 + 1] = tf32f(acc[nt][3]);
            }
        }
        __syncthreads();

        if (h < 7) {
            const float4* gv4 = (const float4*)(g_v + nextbase * (PT * DIM));
            for (int i = tid; i < PT * 32; i += 256) {
                int r = i >> 5, c = i & 31;
                cp16(sv_a + (uint32_t)(r * 132 + c * 4) * 4, gv4 + i);
            }
            cp_commit();
        }

        // ---- out accumulate: Wo fragments via one LDG.128 per ks ----
        {
            const float4* wof = ((const float4*)g_woF) + ((size_t)(wid * 8 + h) * 16) * 32 + lane;
            #pragma unroll
            for (int ks = 0; ks < 16; ks++) {
                int k0 = ks * 8;
                float4 av = __ldg(wof + ks * 32);
                uint32_t a[4] = {__float_as_uint(av.x), __float_as_uint(av.y),
                                 __float_as_uint(av.z), __float_as_uint(av.w)};
                #pragma unroll
                for (int nt = 0; nt < 7; nt++) {
                    uint32_t b[2];
                    b[0] = __float_as_uint(att[(nt * 8 + g) * 132 + k0 + t]);
                    b[1] = __float_as_uint(att[(nt * 8 + g) * 132 + k0 + t + 4]);
                    mma_tf32(acc_o[nt], a, b);
                }
            }
        }
        __syncthreads();

        if (h < 7) {
            const float4* gq4 = (const float4*)(g_q + nextbase * (PT * DIM));
            for (int i = tid; i < PT * 32; i += 256) {
                int r = i >> 5, c = i & 31;
                cp16(sq_a + (uint32_t)(r * 132 + c * 4) * 4, gq4 + i);
            }
            cp_commit();
        }
    }

    // ---- final store ----
    int wy = w >> 4, wx = w & 15;
    float* dst_n = out + (size_t)n * DIM * PPTS;
    #pragma unroll
    for (int rs = 0; rs < 2; rs++) {
        int o = om0 + g + rs * 8;
        float bias = bo[o];
        float* dst = dst_n + (size_t)o * PPTS;
        #pragma unroll
        for (int nt = 0; nt < 7; nt++) {
            #pragma unroll
            for (int cs = 0; cs < 2; cs++) {
                int tok = nt * 8 + 2 * t + cs;
                if (tok < PT) {
                    int jy = tok / WIN, jx = tok - jy * WIN;
                    int p = (wy * WIN + jy) * CWID + wx * WIN + jx;
                    dst[p] = acc_o[nt][rs * 2 + cs] + bias;
                }
            }
        }
    }
}

// ---------------- launch ----------------
extern "C" void kernel_launch(void* const* d_in, const int* in_sizes, int n_in,
                              void* d_out, int out_size) {
    const float* x   = (const float*)d_in[0];
    const float* Wq  = (const float*)d_in[1];
    const float* bq  = (const float*)d_in[2];
    const float* Wk  = (const float*)d_in[3];
    const float* bk  = (const float*)d_in[4];
    const float* Wv  = (const float*)d_in[5];
    const float* bv  = (const float*)d_in[6];
    const float* Wo  = (const float*)d_in[7];
    const float* bo  = (const float*)d_in[8];
    const float* pos = (const float*)d_in[9];
    float* out = (float*)d_out;

    wo_frag_prep<<<512, 256>>>(Wo);
    {
        dim3 gw(128, 3);
        w_prep<<<gw, 256>>>(Wq, Wk, Wv);
    }
    x_prep<<<6272, 256>>>(x);

    {
        static int attr_set = 0;
        if (!attr_set) {
            cudaFuncSetAttribute(qkv_kernel, cudaFuncAttributeMaxDynamicSharedMemorySize,
                                 Q_SM_FLOATS * (int)sizeof(float));
            cudaFuncSetAttribute(attn_out_kernel, cudaFuncAttributeMaxDynamicSharedMemorySize,
                                 SM_FLOATS * (int)sizeof(float));
            attr_set = 1;
        }
    }
    {
        dim3 grid(PPTS / 128, HEADS, 12);
        qkv_kernel<<<grid, 128, Q_SM_FLOATS * sizeof(float)>>>(bq, bk, bv);
    }
    attn_out_kernel<<<NB * WN, 256, SM_FLOATS * sizeof(float)>>>(pos, bo, out);
}

// round 9
// speedup vs baseline: 1.3492x; 1.0362x over previous
#include <cuda_runtime.h>
#include <cuda_bf16.h>
#include <cstdint>

// ---------------- problem constants ----------------
#define NB    4
#define DIM   128
#define HEADS 8
#define PPTS  12544
#define CWID  112
#define WIN   7
#define NWX   16
#define WN    256
#define PT    49

// q,k,v: [n][h][win][tok=49][d=128], values pre-rounded to tf32
__device__ float g_q[(size_t)NB * HEADS * WN * PT * DIM];
__device__ float g_k[(size_t)NB * HEADS * WN * PT * DIM];
__device__ float g_v[(size_t)NB * HEADS * WN * PT * DIM];
__device__ float g_woF[(size_t)DIM * HEADS * DIM];        // Wo, fragment-major, tf32
__device__ float g_wR[(size_t)3 * HEADS * DIM * DIM];     // Wq/Wk/Wv rounded
__device__ float g_xR[(size_t)NB * DIM * PPTS];           // x rounded

__device__ __forceinline__ float tf32f(float x) {
    uint32_t u;
    asm("cvt.rna.tf32.f32 %0, %1;" : "=r"(u) : "f"(x));
    return __uint_as_float(u);
}

__device__ __forceinline__ void mma_tf32(float c[4], const uint32_t a[4], const uint32_t b[2]) {
    asm volatile(
        "mma.sync.aligned.m16n8k8.row.col.f32.tf32.tf32.f32 "
        "{%0,%1,%2,%3}, {%4,%5,%6,%7}, {%8,%9}, {%0,%1,%2,%3};\n"
        : "+f"(c[0]), "+f"(c[1]), "+f"(c[2]), "+f"(c[3])
        : "r"(a[0]), "r"(a[1]), "r"(a[2]), "r"(a[3]), "r"(b[0]), "r"(b[1]));
}

__device__ __forceinline__ void cp16(uint32_t smem_addr, const void* gptr) {
    asm volatile("cp.async.cg.shared.global [%0], [%1], 16;" :: "r"(smem_addr), "l"(gptr));
}
__device__ __forceinline__ void cp_commit() {
    asm volatile("cp.async.commit_group;");
}

// ---------------- prep kernels ----------------
__global__ void wo_frag_prep(const float* __restrict__ Wo) {
    int idx = blockIdx.x * 256 + threadIdx.x;       // 131072 total
    int lane = idx & 31;
    int ks   = (idx >> 5) & 15;
    int h    = (idx >> 9) & 7;
    int wd   = idx >> 12;                           // 0..7
    int g = lane >> 2, t = lane & 3;
    int row = wd * 16 + g;
    int col = h * 128 + ks * 8 + t;
    float4 v;
    v.x = tf32f(Wo[(size_t)row * 1024 + col]);
    v.y = tf32f(Wo[(size_t)(row + 8) * 1024 + col]);
    v.z = tf32f(Wo[(size_t)row * 1024 + col + 4]);
    v.w = tf32f(Wo[(size_t)(row + 8) * 1024 + col + 4]);
    ((float4*)g_woF)[idx] = v;
}
__global__ void w_prep(const float* __restrict__ Wq, const float* __restrict__ Wk,
                       const float* __restrict__ Wv) {
    int i = blockIdx.x * 256 + threadIdx.x;     // 32768 float4 per matrix
    const float* src = (blockIdx.y == 0) ? Wq : (blockIdx.y == 1) ? Wk : Wv;
    float4 v = ((const float4*)src)[i];
    ((float4*)g_wR)[(size_t)blockIdx.y * 32768 + i] =
        make_float4(tf32f(v.x), tf32f(v.y), tf32f(v.z), tf32f(v.w));
}
__global__ void x_prep(const float* __restrict__ x) {
    size_t i = (size_t)blockIdx.x * 256 + threadIdx.x;   // 1,605,632 float4
    float4 v = ((const float4*)x)[i];
    ((float4*)g_xR)[i] = make_float4(tf32f(v.x), tf32f(v.y), tf32f(v.z), tf32f(v.w));
}

// ---------------- Kernel A: QKV projection, 2 p-tiles per block ----------------
// smem: As [128][132] @0 ; Bs [2][32][136] @16896 ; total 25600 floats (102.4 KB)
#define QA_OFF 0
#define QB_OFF 16896
#define Q_SM_FLOATS 25600

__global__ __launch_bounds__(128, 2)
void qkv_kernel(const float* __restrict__ bq, const float* __restrict__ bk,
                const float* __restrict__ bv) {
    extern __shared__ float qsm[];
    float* As = qsm + QA_OFF;                 // [o][k] stride 132
    float* Bs = qsm + QB_OFF;                 // [st][k][p] stride 136

    int z = blockIdx.z;
    int n = z & 3;
    int which = z >> 2;
    const float* bvec = (which == 0) ? bq : (which == 1) ? bk : bv;
    float* garr = (which == 0) ? g_q : (which == 1) ? g_k : g_v;
    int h = blockIdx.y;
    int p_base = blockIdx.x * 256;            // two 128-wide p tiles
    const float* Wsrc = g_wR + (size_t)which * 131072 + (size_t)h * 128 * 128;
    const float* xn = g_xR + (size_t)n * DIM * PPTS;

    int tid = threadIdx.x, lane = tid & 31, wid = tid >> 5;   // 4 warps
    int g = lane >> 2, t = lane & 3;
    int m0w = (wid >> 1) * 64, n0w = (wid & 1) * 64;

    uint32_t As_a = (uint32_t)__cvta_generic_to_shared(As);
    uint32_t Bs_a = (uint32_t)__cvta_generic_to_shared(Bs);

    // full-A copy + B chunk 0 (group 0)
    #pragma unroll
    for (int r = 0; r < 32; r++) {
        int i = tid + r * 128;                // 4096 chunks
        int row = i >> 5, c = i & 31;
        cp16(As_a + (uint32_t)(row * 132 + c * 4) * 4, Wsrc + (size_t)row * 128 + c * 4);
    }
    #pragma unroll
    for (int r = 0; r < 8; r++) {
        int i = tid + r * 128;                // 1024 chunks
        int kk = i >> 5, c = i & 31;
        cp16(Bs_a + (uint32_t)(kk * 136 + c * 4) * 4, xn + (size_t)kk * PPTS + p_base + c * 4);
    }
    cp_commit();

    float acc[4][8][4] = {};
    size_t headbase = ((size_t)n * HEADS + h) * WN;
    float biasr[4][2];
    #pragma unroll
    for (int mf = 0; mf < 4; mf++)
        #pragma unroll
        for (int rs = 0; rs < 2; rs++)
            biasr[mf][rs] = bvec[h * 128 + m0w + mf * 16 + rs * 8 + g];

    // chunks 0..7: (c>>2) = p tile, (c&3) = k chunk
    #pragma unroll
    for (int c = 0; c < 8; c++) {
        int st = c & 1;
        if (c < 7) {
            int nst = (c + 1) & 1;
            int k0n = ((c + 1) & 3) * 32;
            int pbn = p_base + ((c + 1) >> 2) * 128;
            #pragma unroll
            for (int r = 0; r < 8; r++) {
                int i = tid + r * 128;
                int kk = i >> 5, cc = i & 31;
                cp16(Bs_a + (uint32_t)(nst * 32 * 136 + kk * 136 + cc * 4) * 4,
                     xn + (size_t)(k0n + kk) * PPTS + pbn + cc * 4);
            }
            cp_commit();
            asm volatile("cp.async.wait_group 1;");
        } else {
            asm volatile("cp.async.wait_group 0;");
        }
        __syncthreads();

        const float* Bst = Bs + st * (32 * 136);
        int acol = (c & 3) * 32;
        #pragma unroll
        for (int ks = 0; ks < 4; ks++) {
            int k0 = ks * 8;
            uint32_t af[4][4], bf[8][2];
            #pragma unroll
            for (int mf = 0; mf < 4; mf++) {
                int m = m0w + mf * 16;
                af[mf][0] = __float_as_uint(As[(m + g) * 132 + acol + k0 + t]);
                af[mf][1] = __float_as_uint(As[(m + g + 8) * 132 + acol + k0 + t]);
                af[mf][2] = __float_as_uint(As[(m + g) * 132 + acol + k0 + t + 4]);
                af[mf][3] = __float_as_uint(As[(m + g + 8) * 132 + acol + k0 + t + 4]);
            }
            #pragma unroll
            for (int nf = 0; nf < 8; nf++) {
                int nn = n0w + nf * 8 + g;
                bf[nf][0] = __float_as_uint(Bst[(k0 + t) * 136 + nn]);
                bf[nf][1] = __float_as_uint(Bst[(k0 + t + 4) * 136 + nn]);
            }
            #pragma unroll
            for (int mf = 0; mf < 4; mf++)
                #pragma unroll
                for (int nf = 0; nf < 8; nf++)
                    mma_tf32(acc[mf][nf], af[mf], bf[nf]);
        }
        __syncthreads();

        // epilogue at end of each p tile (c==3, c==7); overlaps next prefetch
        if ((c & 3) == 3) {
            int pb = p_base + (c >> 2) * 128;
            #pragma unroll
            for (int nf = 0; nf < 8; nf++) {
                #pragma unroll
                for (int cs = 0; cs < 2; cs++) {
                    int p = pb + n0w + nf * 8 + 2 * t + cs;
                    int pr = p / CWID, pc = p - pr * CWID;
                    int win = (pr / WIN) * NWX + (pc / WIN);
                    int tok = (pr % WIN) * WIN + (pc % WIN);
                    float* base = garr + ((headbase + win) * PT + tok) * DIM;
                    #pragma unroll
                    for (int mf = 0; mf < 4; mf++)
                        #pragma unroll
                        for (int rs = 0; rs < 2; rs++) {
                            int d = m0w + mf * 16 + rs * 8 + g;
                            base[d] = tf32f(acc[mf][nf][rs * 2 + cs] + biasr[mf][rs]);
                        }
                }
            }
            if (c == 3) {
                #pragma unroll
                for (int mf = 0; mf < 4; mf++)
                    #pragma unroll
                    for (int nf = 0; nf < 8; nf++)
                        #pragma unroll
                        for (int r = 0; r < 4; r++)
                            acc[mf][nf][r] = 0.f;
            }
        }
    }
}

// ---------------- Kernel B: fused attention + output projection ----------------
#define SQ_OFF  0          // sq/att [64][132]  (aliased)
#define SK_OFF  8448       // sk  [56][132]
#define SV_OFF  15840      // sv  [56][132] (rows 49..55 zeroed once)
#define SS_OFF  23232      // S   [64][60]
#define SB_OFF  27072      // sball [8][176]
#define SM_FLOATS 28480    // 113,920 B

__global__ __launch_bounds__(256, 2)
void attn_out_kernel(const float* __restrict__ pos_code,
                     const float* __restrict__ bo,
                     float* __restrict__ out) {
    extern __shared__ float sm[];
    float* sq    = sm + SQ_OFF;
    float* sk    = sm + SK_OFF;
    float* sv    = sm + SV_OFF;
    float* att   = sm + SQ_OFF;       // alias: q dead after QK
    float* S     = sm + SS_OFF;
    float* sball = sm + SB_OFF;

    int bid = blockIdx.x;
    int w = bid & 255;
    int n = bid >> 8;
    int tid = threadIdx.x, lane = tid & 31, wid = tid >> 5;
    int g = lane >> 2, t = lane & 3;
    int m0 = (wid >> 1) * 16;
    int half = wid & 1;
    int om0 = wid * 16;

    uint32_t sq_a = (uint32_t)__cvta_generic_to_shared(sq);
    uint32_t sk_a = (uint32_t)__cvta_generic_to_shared(sk);
    uint32_t sv_a = (uint32_t)__cvta_generic_to_shared(sv);

    size_t winbase = ((size_t)n * HEADS) * WN + w;

    for (int i = tid; i < 7 * 132; i += 256) sv[49 * 132 + i] = 0.f;
    // preload all 8 heads' bias tables (coalesced)
    for (int j = tid; j < 169 * HEADS; j += 256) {
        int hh = j & 7, ii = j >> 3;
        sball[hh * 176 + ii] = pos_code[j];
    }

    {
        const float4* gq4 = (const float4*)(g_q + winbase * (PT * DIM));
        const float4* gk4 = (const float4*)(g_k + winbase * (PT * DIM));
        const float4* gv4 = (const float4*)(g_v + winbase * (PT * DIM));
        for (int i = tid; i < PT * 32; i += 256) {
            int r = i >> 5, c = i & 31;
            uint32_t off = (uint32_t)(r * 132 + c * 4) * 4;
            cp16(sq_a + off, gq4 + i);
            cp16(sk_a + off, gk4 + i);
            cp16(sv_a + off, gv4 + i);
        }
        cp_commit();
    }

    float acc_o[7][4] = {};
    const float scale = 0.08838834764831845f;

    for (int h = 0; h < 8; h++) {
        asm volatile("cp.async.wait_group 0;");
        __syncthreads();

        const float* sb = sball + h * 176;
        size_t nextbase = winbase + (size_t)(h + 1) * WN;

        // ---- QK ----
        {
            float acc[4][4] = {};
            #pragma unroll
            for (int ks = 0; ks < 16; ks++) {
                int k0 = ks * 8;
                uint32_t a[4];
                a[0] = __float_as_uint(sq[(m0 + g) * 132 + k0 + t]);
                a[1] = __float_as_uint(sq[(m0 + g + 8) * 132 + k0 + t]);
                a[2] = __float_as_uint(sq[(m0 + g) * 132 + k0 + t + 4]);
                a[3] = __float_as_uint(sq[(m0 + g + 8) * 132 + k0 + t + 4]);
                #pragma unroll
                for (int nt = 0; nt < 4; nt++) {
                    int nti = half * 4 + nt;
                    if (nti >= 7) break;
                    int n0 = nti * 8;
                    uint32_t b[2];
                    b[0] = __float_as_uint(sk[(n0 + g) * 132 + k0 + t]);
                    b[1] = __float_as_uint(sk[(n0 + g) * 132 + k0 + t + 4]);
                    mma_tf32(acc[nt], a, b);
                }
            }
            #pragma unroll
            for (int nt = 0; nt < 4; nt++) {
                int nti = half * 4 + nt;
                if (nti >= 7) break;
                int n0 = nti * 8;
                S[(m0 + g) * 60 + n0 + 2 * t]     = acc[nt][0];
                S[(m0 + g) * 60 + n0 + 2 * t + 1] = acc[nt][1];
                S[(m0 + g + 8) * 60 + n0 + 2 * t]     = acc[nt][2];
                S[(m0 + g + 8) * 60 + n0 + 2 * t + 1] = acc[nt][3];
            }
        }
        __syncthreads();

        if (h < 7) {
            const float4* gk4 = (const float4*)(g_k + nextbase * (PT * DIM));
            for (int i = tid; i < PT * 32; i += 256) {
                int r = i >> 5, c = i & 31;
                cp16(sk_a + (uint32_t)(r * 132 + c * 4) * 4, gk4 + i);
            }
            cp_commit();
        }

        // ---- softmax ----
        for (int j = wid; j < PT; j += 8) {
            int yj = j / WIN, xj = j - yj * WIN;
            float* row = S + j * 60;
            int i0 = lane;
            int y0 = i0 / WIN, x0 = i0 - y0 * WIN;
            int r0 = (y0 - yj + WIN - 1) + (x0 - xj + WIN - 1) * (2 * WIN - 1);
            float v0 = row[i0] * scale + sb[r0];
            float v1 = -1e30f;
            int i1 = lane + 32;
            if (i1 < PT) {
                int y1 = i1 / WIN, x1 = i1 - y1 * WIN;
                int r1 = (y1 - yj + WIN - 1) + (x1 - xj + WIN - 1) * (2 * WIN - 1);
                v1 = row[i1] * scale + sb[r1];
            }
            float m = fmaxf(v0, v1);
            #pragma unroll
            for (int off = 16; off; off >>= 1) m = fmaxf(m, __shfl_xor_sync(0xffffffffu, m, off));
            float e0 = __expf(v0 - m);
            float e1 = (i1 < PT) ? __expf(v1 - m) : 0.f;
            float s = e0 + e1;
            #pragma unroll
            for (int off = 16; off; off >>= 1) s += __shfl_xor_sync(0xffffffffu, s, off);
            float inv = 1.f / s;
            row[i0] = tf32f(e0 * inv);
            if (i1 < PT) row[i1] = tf32f(e1 * inv);
            else if (i1 < 56) row[i1] = 0.f;
        }
        __syncthreads();

        // ---- PV ----
        {
            float acc[8][4] = {};
            #pragma unroll
            for (int ks = 0; ks < 7; ks++) {
                int k0 = ks * 8;
                uint32_t a[4];
                a[0] = __float_as_uint(S[(m0 + g) * 60 + k0 + t]);
                a[1] = __float_as_uint(S[(m0 + g + 8) * 60 + k0 + t]);
                a[2] = __float_as_uint(S[(m0 + g) * 60 + k0 + t + 4]);
                a[3] = __float_as_uint(S[(m0 + g + 8) * 60 + k0 + t + 4]);
                #pragma unroll
                for (int nt = 0; nt < 8; nt++) {
                    int n0 = (half * 8 + nt) * 8;
                    uint32_t b[2];
                    b[0] = __float_as_uint(sv[(k0 + t) * 132 + n0 + g]);
                    b[1] = __float_as_uint(sv[(k0 + t + 4) * 132 + n0 + g]);
                    mma_tf32(acc[nt], a, b);
                }
            }
            #pragma unroll
            for (int nt = 0; nt < 8; nt++) {
                int d0 = (half * 8 + nt) * 8 + 2 * t;
                att[(m0 + g) * 132 + d0]         = tf32f(acc[nt][0]);
                att[(m0 + g) * 132 + d0 + 1]     = tf32f(acc[nt][1]);
                att[(m0 + g + 8) * 132 + d0]     = tf32f(acc[nt][2]);
                att[(m0 + g + 8) * 132 + d0 + 1] = tf32f(acc[nt][3]);
            }
        }
        __syncthreads();

        if (h < 7) {
            const float4* gv4 = (const float4*)(g_v + nextbase * (PT * DIM));
            for (int i = tid; i < PT * 32; i += 256) {
                int r = i >> 5, c = i & 31;
                cp16(sv_a + (uint32_t)(r * 132 + c * 4) * 4, gv4 + i);
            }
            cp_commit();
        }

        // ---- out accumulate: Wo fragments via one LDG.128 per ks ----
        {
            const float4* wof = ((const float4*)g_woF) + ((size_t)(wid * 8 + h) * 16) * 32 + lane;
            #pragma unroll
            for (int ks = 0; ks < 16; ks++) {
                int k0 = ks * 8;
                float4 av = __ldg(wof + ks * 32);
                uint32_t a[4] = {__float_as_uint(av.x), __float_as_uint(av.y),
                                 __float_as_uint(av.z), __float_as_uint(av.w)};
                #pragma unroll
                for (int nt = 0; nt < 7; nt++) {
                    uint32_t b[2];
                    b[0] = __float_as_uint(att[(nt * 8 + g) * 132 + k0 + t]);
                    b[1] = __float_as_uint(att[(nt * 8 + g) * 132 + k0 + t + 4]);
                    mma_tf32(acc_o[nt], a, b);
                }
            }
        }
        __syncthreads();

        if (h < 7) {
            const float4* gq4 = (const float4*)(g_q + nextbase * (PT * DIM));
            for (int i = tid; i < PT * 32; i += 256) {
                int r = i >> 5, c = i & 31;
                cp16(sq_a + (uint32_t)(r * 132 + c * 4) * 4, gq4 + i);
            }
            cp_commit();
        }
    }

    // ---- final store ----
    int wy = w >> 4, wx = w & 15;
    float* dst_n = out + (size_t)n * DIM * PPTS;
    #pragma unroll
    for (int rs = 0; rs < 2; rs++) {
        int o = om0 + g + rs * 8;
        float bias = bo[o];
        float* dst = dst_n + (size_t)o * PPTS;
        #pragma unroll
        for (int nt = 0; nt < 7; nt++) {
            #pragma unroll
            for (int cs = 0; cs < 2; cs++) {
                int tok = nt * 8 + 2 * t + cs;
                if (tok < PT) {
                    int jy = tok / WIN, jx = tok - jy * WIN;
                    int p = (wy * WIN + jy) * CWID + wx * WIN + jx;
                    dst[p] = acc_o[nt][rs * 2 + cs] + bias;
                }
            }
        }
    }
}

// ---------------- launch ----------------
extern "C" void kernel_launch(void* const* d_in, const int* in_sizes, int n_in,
                              void* d_out, int out_size) {
    const float* x   = (const float*)d_in[0];
    const float* Wq  = (const float*)d_in[1];
    const float* bq  = (const float*)d_in[2];
    const float* Wk  = (const float*)d_in[3];
    const float* bk  = (const float*)d_in[4];
    const float* Wv  = (const float*)d_in[5];
    const float* bv  = (const float*)d_in[6];
    const float* Wo  = (const float*)d_in[7];
    const float* bo  = (const float*)d_in[8];
    const float* pos = (const float*)d_in[9];
    float* out = (float*)d_out;

    wo_frag_prep<<<512, 256>>>(Wo);
    {
        dim3 gw(128, 3);
        w_prep<<<gw, 256>>>(Wq, Wk, Wv);
    }
    x_prep<<<6272, 256>>>(x);

    {
        static int attr_set = 0;
        if (!attr_set) {
            cudaFuncSetAttribute(qkv_kernel, cudaFuncAttributeMaxDynamicSharedMemorySize,
                                 Q_SM_FLOATS * (int)sizeof(float));
            cudaFuncSetAttribute(attn_out_kernel, cudaFuncAttributeMaxDynamicSharedMemorySize,
                                 SM_FLOATS * (int)sizeof(float));
            attr_set = 1;
        }
    }
    {
        dim3 grid(PPTS / 256, HEADS, 12);
        qkv_kernel<<<grid, 128, Q_SM_FLOATS * sizeof(float)>>>(bq, bk, bv);
    }
    attn_out_kernel<<<NB * WN, 256, SM_FLOATS * sizeof(float)>>>(pos, bo, out);
}